// round 14
// baseline (speedup 1.0000x reference)
#include <cuda_runtime.h>
#include <cuda_fp16.h>
#include <cstdint>
#include <math.h>

// ---------------------------------------------------------------------------
// Problem constants
// ---------------------------------------------------------------------------
#define HID 128
#define NHEAD 8
#define HDIM 16

#define NH_MAX 8000
#define NI_MAX 40000
#define NT_MAX 20000
#define NN_MAX (NH_MAX + NI_MAX + NT_MAX)
#define NREL_MAX (NH_MAX + 2*NI_MAX + NT_MAX)
#define MAXE 250000

#define KH 400
#define KI 304
#define KT 200
#define XI_TOTAL ((size_t)NH_MAX*KH + (size_t)NI_MAX*KI + (size_t)NT_MAX*KT)

// fp16 weight pool offsets (transposed [128][Kp])
#define WH_OFF 0
#define WI_OFF 51200
#define WT_OFF 90112
#define WQ_OFF 115712
#define WF_OFF 164864
#define WA_OFF 295936
#define WO_OFF 345088
#define WPOOL  361472

// ---------------------------------------------------------------------------
// Device scratch
// ---------------------------------------------------------------------------
__device__ float g_q    [(size_t)NN_MAX   * HID];
__device__ float g_krel [(size_t)NREL_MAX * HID];
__device__ float g_vrel [(size_t)NREL_MAX * HID];
__device__ float g_bf   [8 * HID];

__device__ int g_deg   [NN_MAX];
__device__ int g_rowptr[NN_MAX + 1];
__device__ int g_pos   [NN_MAX];
__device__ int g_erec  [4 * MAXE];
__device__ int g_bsum  [512];

__device__ __half g_xih[XI_TOTAL];
__device__ __half g_xil[XI_TOTAL];
__device__ __half g_xsh[(size_t)NN_MAX * HID];
__device__ __half g_xsl[(size_t)NN_MAX * HID];
__device__ __half g_gbh[(size_t)NN_MAX * HID];
__device__ __half g_gbl[(size_t)NN_MAX * HID];
__device__ __half g_hth[(size_t)NH_MAX * HID];
__device__ __half g_htl[(size_t)NH_MAX * HID];
__device__ __half g_wth[WPOOL];

// ---------------------------------------------------------------------------
// Fuse Wk/Wv with relation matrices; p_rel/sqrtD folded into k-kind.
// Writes TRANSPOSED fp16 into the weight pool.
// ---------------------------------------------------------------------------
__global__ void fuse_rel_weights(const float* __restrict__ Wk, const float* __restrict__ bk,
                                 const float* __restrict__ Wv, const float* __restrict__ bv,
                                 const float* __restrict__ a_rel, const float* __restrict__ m_rel,
                                 const float* __restrict__ prel,
                                 __half* __restrict__ wth, float* __restrict__ bf)
{
    int slot = blockIdx.x;
    int e = slot >> 1, kind = slot & 1;
    int s = (e == 0) ? 0 : ((e == 3) ? 2 : 1);
    const float* Wb = (kind ? Wv : Wk) + (size_t)s * HID * HID;
    const float* bb = (kind ? bv : bk) + (size_t)s * HID;
    const float* rel = (kind ? m_rel : a_rel) + (size_t)e * NHEAD * HDIM * HDIM;

    for (int idx = threadIdx.x; idx < HID * HID; idx += blockDim.x) {
        int i = idx >> 7, j = idx & 127;
        int h = j >> 4, j16 = j & 15;
        float acc = 0.0f;
        #pragma unroll
        for (int d = 0; d < HDIM; ++d)
            acc += Wb[i * HID + h * HDIM + d] * rel[(h * HDIM + d) * HDIM + j16];
        if (kind == 0) acc *= prel[e * NHEAD + h] * 0.25f;
        wth[(size_t)WF_OFF + (size_t)slot * 16384 + j * 128 + i] = __float2half_rn(acc);
    }
    for (int j = threadIdx.x; j < HID; j += blockDim.x) {
        int h = j >> 4, j16 = j & 15;
        float acc = 0.0f;
        #pragma unroll
        for (int d = 0; d < HDIM; ++d)
            acc += bb[h * HDIM + d] * rel[(h * HDIM + d) * HDIM + j16];
        if (kind == 0) acc *= prel[e * NHEAD + h] * 0.25f;
        bf[slot * HID + j] = acc;
    }
}

// ---------------------------------------------------------------------------
// fp32 -> fp16 hi/lo, vectorized, with K padding
// ---------------------------------------------------------------------------
__global__ void convert_pad4(const float* __restrict__ src,
                             __half* __restrict__ dh, __half* __restrict__ dl,
                             int M, int K, int Kp)
{
    int idx4 = blockIdx.x * blockDim.x + threadIdx.x;
    int kq = Kp >> 2;
    if (idx4 >= M * kq) return;
    int r = idx4 / kq, k4 = (idx4 - r * kq) << 2;
    float4 v = make_float4(0.f, 0.f, 0.f, 0.f);
    if (k4 < K)
        v = *reinterpret_cast<const float4*>(src + (size_t)r * K + k4);
    __half2 h01, h23, l01, l23;
    h01.x = __float2half_rn(v.x); h01.y = __float2half_rn(v.y);
    h23.x = __float2half_rn(v.z); h23.y = __float2half_rn(v.w);
    l01.x = __float2half_rn(v.x - __half2float(h01.x));
    l01.y = __float2half_rn(v.y - __half2float(h01.y));
    l23.x = __float2half_rn(v.z - __half2float(h23.x));
    l23.y = __float2half_rn(v.w - __half2float(h23.y));
    *reinterpret_cast<__half2*>(dh + (size_t)idx4 * 4)     = h01;
    *reinterpret_cast<__half2*>(dh + (size_t)idx4 * 4 + 2) = h23;
    *reinterpret_cast<__half2*>(dl + (size_t)idx4 * 4)     = l01;
    *reinterpret_cast<__half2*>(dl + (size_t)idx4 * 4 + 2) = l23;
}

// ---------------------------------------------------------------------------
// Weight transpose + fp16
// ---------------------------------------------------------------------------
struct TJob { const float* W; __half* th; int K; int Kp; };
struct TJobs { TJob j[10]; };

__global__ void transpose_wt(TJobs jobs)
{
    TJob jb = jobs.j[blockIdx.y];
    int total = 128 * jb.Kp;
    for (int idx = blockIdx.x * blockDim.x + threadIdx.x; idx < total;
         idx += gridDim.x * blockDim.x) {
        int n = idx / jb.Kp, k = idx - n * jb.Kp;
        float v = (k < jb.K) ? jb.W[(size_t)k * 128 + n] : 0.0f;
        jb.th[idx] = __float2half_rn(v);
    }
}

// ---------------------------------------------------------------------------
// CSR build
// ---------------------------------------------------------------------------
struct EArr { const int* src[4]; const int* dst[4]; int E[4]; int base[4]; int slot[4]; };

__global__ void zero_deg(int* __restrict__ deg, int NN)
{
    int i = blockIdx.x * blockDim.x + threadIdx.x;
    if (i < NN) deg[i] = 0;
}

__global__ void hist_deg(EArr ea, int* __restrict__ deg)
{
    int e = blockIdx.y;
    const int* dst = ea.dst[e];
    int E = ea.E[e], base = ea.base[e];
    for (int i = blockIdx.x * blockDim.x + threadIdx.x; i < E;
         i += gridDim.x * blockDim.x)
        atomicAdd(&deg[base + dst[i]], 1);
}

__global__ void scan1(const int* __restrict__ deg, int* __restrict__ rowptr,
                      int* __restrict__ bsum, int NN)
{
    __shared__ int ws[8];
    int i = blockIdx.x * 256 + threadIdx.x;
    int lane = threadIdx.x & 31, w = threadIdx.x >> 5;
    int x = (i < NN) ? deg[i] : 0;
    #pragma unroll
    for (int o = 1; o < 32; o <<= 1) {
        int y = __shfl_up_sync(0xffffffffu, x, o);
        if (lane >= o) x += y;
    }
    if (lane == 31) ws[w] = x;
    __syncthreads();
    if (threadIdx.x < 8) {
        int y = ws[threadIdx.x];
        #pragma unroll
        for (int o = 1; o < 8; o <<= 1) {
            int z = __shfl_up_sync(0xffu, y, o);
            if ((int)threadIdx.x >= o) y += z;
        }
        ws[threadIdx.x] = y;
    }
    __syncthreads();
    if (w > 0) x += ws[w - 1];
    if (i < NN) rowptr[i + 1] = x;
    if (threadIdx.x == 255) bsum[blockIdx.x] = x;
}

__global__ void scan2(int* __restrict__ bsum, int NB)
{
    __shared__ int s[512];
    int t = threadIdx.x;
    int orig = (t < NB) ? bsum[t] : 0;
    s[t] = orig;
    __syncthreads();
    for (int o = 1; o < 512; o <<= 1) {
        int v = (t >= o) ? s[t - o] : 0;
        __syncthreads();
        s[t] += v;
        __syncthreads();
    }
    if (t < NB) bsum[t] = s[t] - orig;
}

__global__ void scan3(const int* __restrict__ deg, int* __restrict__ rowptr,
                      const int* __restrict__ bsum, int* __restrict__ pos, int NN)
{
    int i = blockIdx.x * 256 + threadIdx.x;
    if (i >= NN) return;
    int val = rowptr[i + 1] + bsum[blockIdx.x];
    rowptr[i + 1] = val;
    pos[i] = val - deg[i];
    if (i == 0) rowptr[0] = 0;
}

__global__ void scatter_edges(EArr ea, int* __restrict__ pos, int* __restrict__ erec)
{
    int e = blockIdx.y;
    const int* src = ea.src[e];
    const int* dst = ea.dst[e];
    int E = ea.E[e], base = ea.base[e], slot = ea.slot[e];
    for (int i = blockIdx.x * blockDim.x + threadIdx.x; i < E;
         i += gridDim.x * blockDim.x) {
        int p = atomicAdd(&pos[base + dst[i]], 1);
        erec[p] = slot + src[i];
    }
}

// ---------------------------------------------------------------------------
// Fused attention (no running max — logits sigma~1 by construction, overflow
// needs 25+ sigma). One warp per dst node. Writes gelu(agg/den) fp16 h/l.
// ---------------------------------------------------------------------------
__global__ __launch_bounds__(256)
void attend(const int* __restrict__ rowptr, const int* __restrict__ erec,
            const float* __restrict__ q, const float* __restrict__ krel,
            const float* __restrict__ vrel,
            __half* __restrict__ oh, __half* __restrict__ ol,
            int n0, int n1)
{
    const int n = n0 + ((blockIdx.x * blockDim.x + threadIdx.x) >> 5);
    const int lane = threadIdx.x & 31;
    if (n >= n1) return;

    const int lo = rowptr[n], hi = rowptr[n + 1];
    const float4 qv = *reinterpret_cast<const float4*>(q + (size_t)n * HID + lane * 4);

    float den = 0.0f;
    float4 acc = make_float4(0.f, 0.f, 0.f, 0.f);

    float4 k0, v0, k1, v1;
    if (lo < hi) {
        int ss = __ldg(erec + lo);
        k0 = *reinterpret_cast<const float4*>(krel + (size_t)ss * HID + lane * 4);
        v0 = *reinterpret_cast<const float4*>(vrel + (size_t)ss * HID + lane * 4);
    }
    if (lo + 1 < hi) {
        int ss = __ldg(erec + lo + 1);
        k1 = *reinterpret_cast<const float4*>(krel + (size_t)ss * HID + lane * 4);
        v1 = *reinterpret_cast<const float4*>(vrel + (size_t)ss * HID + lane * 4);
    }
    for (int i = lo; i < hi; ++i) {
        float4 kv = k0, vv = v0;
        k0 = k1; v0 = v1;
        if (i + 2 < hi) {
            int ss = __ldg(erec + i + 2);
            k1 = *reinterpret_cast<const float4*>(krel + (size_t)ss * HID + lane * 4);
            v1 = *reinterpret_cast<const float4*>(vrel + (size_t)ss * HID + lane * 4);
        }
        float p = qv.x * kv.x + qv.y * kv.y + qv.z * kv.z + qv.w * kv.w;
        p += __shfl_xor_sync(0xffffffffu, p, 1);
        p += __shfl_xor_sync(0xffffffffu, p, 2);
        float ex = __expf(p);
        den += ex;
        acc.x = fmaf(ex, vv.x, acc.x);
        acc.y = fmaf(ex, vv.y, acc.y);
        acc.z = fmaf(ex, vv.z, acc.z);
        acc.w = fmaf(ex, vv.w, acc.w);
    }

    const float inv = 1.0f / (den + 1e-16f);
    float o[4] = { acc.x * inv, acc.y * inv, acc.z * inv, acc.w * inv };
    #pragma unroll
    for (int j = 0; j < 4; ++j)
        o[j] = 0.5f * o[j] * (1.0f + erff(o[j] * 0.70710678118654752f));
    __half2 h01, h23, l01, l23;
    h01.x = __float2half_rn(o[0]); h01.y = __float2half_rn(o[1]);
    h23.x = __float2half_rn(o[2]); h23.y = __float2half_rn(o[3]);
    l01.x = __float2half_rn(o[0] - __half2float(h01.x));
    l01.y = __float2half_rn(o[1] - __half2float(h01.y));
    l23.x = __float2half_rn(o[2] - __half2float(h23.x));
    l23.y = __float2half_rn(o[3] - __half2float(h23.y));
    size_t ob = (size_t)n * HID + lane * 4;
    *reinterpret_cast<__half2*>(oh + ob)     = h01;
    *reinterpret_cast<__half2*>(oh + ob + 2) = h23;
    *reinterpret_cast<__half2*>(ol + ob)     = l01;
    *reinterpret_cast<__half2*>(ol + ob + 2) = l23;
}

// ---------------------------------------------------------------------------
// Shared GEMM building blocks
// ---------------------------------------------------------------------------
#define KC 32
#define PADK 40
#define CHB (128 * PADK)
#define TG_SMEM (6 * CHB * 2)       // tgemm: 2 stages x 3 arrays
#define PC_SMEM (10 * CHB * 2)      // projchain: A h/l (8 chunks) + B 2 stages

__device__ __forceinline__ uint32_t smem_u32(const void* p) {
    uint32_t a;
    asm("{ .reg .u64 t; cvta.to.shared.u64 t, %1; cvt.u32.u64 %0, t; }" : "=r"(a) : "l"(p));
    return a;
}

#define CPASYNC(dst, src, sz)                                                 \
    asm volatile("cp.async.ca.shared.global [%0], [%1], 16, %2;"              \
        :: "r"(dst), "l"(src), "r"(sz))

#define LDSM4(r0, r1, r2, r3, addr)                                           \
    asm volatile("ldmatrix.sync.aligned.m8n8.x4.shared.b16 {%0,%1,%2,%3}, [%4];" \
        : "=r"(r0), "=r"(r1), "=r"(r2), "=r"(r3) : "r"(addr))

#define MMA_FP16(d, a, b)                                                     \
    asm volatile("mma.sync.aligned.m16n8k16.row.col.f32.f16.f16.f32 "         \
        "{%0,%1,%2,%3}, {%4,%5,%6,%7}, {%8,%9}, {%0,%1,%2,%3};"               \
        : "+f"((d)[0]), "+f"((d)[1]), "+f"((d)[2]), "+f"((d)[3])              \
        : "r"((a)[0]), "r"((a)[1]), "r"((a)[2]), "r"((a)[3]),                 \
          "r"((b)[0]), "r"((b)[1]))

// ---------------------------------------------------------------------------
// projchain: per 128-row tile, compute xs = x @ W_in + b (2-term fp16),
// keep xs in SMEM (4 K-chunks, h/l), then run all of this type's projections
// (q 2-term; kr/vr 1-term) streaming only B. Writes xs h/l to global too
// (GEMM3 skip gate needs it).
// ---------------------------------------------------------------------------
struct PProj { const __half* B; const float* bias; float* dst; int oneterm; };
struct PJob  { const __half *Ah, *Al, *Bin; const float* bias_in;
               __half *xh, *xl; int M, Kin, nproj, blk0; PProj p[5]; };
struct PJobs { PJob j[2]; int njobs; };

__global__ __launch_bounds__(256, 2)
void projchain(PJobs jobs)
{
    extern __shared__ __half sm[];
    const uint32_t base = smem_u32(sm);
    const int tid = threadIdx.x;
    const int wid = tid >> 5, lane = tid & 31;
    const int wm = wid & 1, wn = wid >> 1;

    int ji = 0;
    if (jobs.njobs > 1 && (int)blockIdx.x >= jobs.j[1].blk0) ji = 1;
    const PJob& jb = jobs.j[ji];
    const int m0 = ((int)blockIdx.x - jb.blk0) * 128;
    const int M = jb.M, Kin = jb.Kin;

    float acc[4][4][4];
    #pragma unroll
    for (int mi = 0; mi < 4; ++mi)
        #pragma unroll
        for (int ni = 0; ni < 4; ++ni)
            #pragma unroll
            for (int r = 0; r < 4; ++r) acc[mi][ni][r] = 0.0f;

    const int a_row = ((lane >> 3) & 1) * 8 + (lane & 7);
    const int a_col = (lane >> 4) * 8;
    const int b_row = (lane >> 4) * 8 + (lane & 7);
    const int b_col = ((lane >> 3) & 1) * 8;
    const int lr = tid >> 2;
    const int lk = (tid & 3) * 8;
    const int r4 = lane >> 2, c2 = (lane & 3) * 2;

    // ---------------- phase 1: xs tile (2-term, K = Kin) ----------------
    {
        const __half* Ah = jb.Ah;
        const __half* Al = jb.Al;
        const __half* B  = jb.Bin;
        const int kch = (Kin + KC - 1) / KC;

        auto load_chunk = [&](int c, int b) {
            const int k0 = c * KC;
            const uint32_t bb = base + (uint32_t)b * (3 * CHB * 2);
            #pragma unroll
            for (int i = 0; i < 2; ++i) {
                int r = lr + i * 64;
                int gk = k0 + lk;
                uint32_t off = (uint32_t)(r * PADK + lk) * 2;
                int okA = (m0 + r < M) && (gk < Kin) ? 16 : 0;
                size_t aoff = okA ? ((size_t)(m0 + r) * Kin + gk) : 0;
                CPASYNC(bb + off,               Ah + aoff, okA);
                CPASYNC(bb + off + CHB * 2,     Al + aoff, okA);
                int okB = (gk < Kin) ? 16 : 0;
                size_t boff = okB ? ((size_t)r * Kin + gk) : 0;
                CPASYNC(bb + off + 2 * CHB * 2, B + boff, okB);
            }
            asm volatile("cp.async.commit_group;" ::: "memory");
        };

        load_chunk(0, 0);
        for (int c = 0; c < kch; ++c) {
            const int b = c & 1;
            asm volatile("cp.async.wait_group 0;" ::: "memory");
            __syncthreads();
            if (c + 1 < kch) load_chunk(c + 1, b ^ 1);

            const uint32_t bb = base + (uint32_t)b * (3 * CHB * 2);
            #pragma unroll
            for (int kk = 0; kk < 2; ++kk) {
                uint32_t ah[4][4], al[4][4], bf2[4][2];
                #pragma unroll
                for (int mi = 0; mi < 4; ++mi) {
                    int row = wm * 64 + mi * 16 + a_row;
                    int col = kk * 16 + a_col;
                    uint32_t off = bb + (uint32_t)(row * PADK + col) * 2;
                    LDSM4(ah[mi][0], ah[mi][1], ah[mi][2], ah[mi][3], off);
                    LDSM4(al[mi][0], al[mi][1], al[mi][2], al[mi][3], off + CHB * 2);
                }
                #pragma unroll
                for (int p2 = 0; p2 < 2; ++p2) {
                    int row = wn * 32 + p2 * 16 + b_row;
                    int col = kk * 16 + b_col;
                    uint32_t off = bb + 2 * CHB * 2 + (uint32_t)(row * PADK + col) * 2;
                    LDSM4(bf2[2*p2][0], bf2[2*p2][1], bf2[2*p2+1][0], bf2[2*p2+1][1], off);
                }
                #pragma unroll
                for (int mi = 0; mi < 4; ++mi)
                    #pragma unroll
                    for (int ni = 0; ni < 4; ++ni) {
                        MMA_FP16(acc[mi][ni], ah[mi], bf2[ni]);
                        MMA_FP16(acc[mi][ni], al[mi], bf2[ni]);
                    }
            }
        }
    }
    // all warps done reading phase-1 buffers before we clobber them with A
    __syncthreads();

    // phase-1 epilogue: xs = acc + bias; write global h/l AND smem A-chunks
    {
        const float* bias = jb.bias_in;
        #pragma unroll
        for (int mi = 0; mi < 4; ++mi) {
            #pragma unroll
            for (int ni = 0; ni < 4; ++ni) {
                int gcol = wn * 32 + ni * 8 + c2;
                float2 bb2 = *reinterpret_cast<const float2*>(bias + gcol);
                #pragma unroll
                for (int half = 0; half < 2; ++half) {
                    int lrow = wm * 64 + mi * 16 + r4 + half * 8;
                    int gr = m0 + lrow;
                    float ox = acc[mi][ni][half * 2 + 0] + bb2.x;
                    float oy = acc[mi][ni][half * 2 + 1] + bb2.y;
                    __half2 h2, l2;
                    h2.x = __float2half_rn(ox);
                    h2.y = __float2half_rn(oy);
                    l2.x = __float2half_rn(ox - __half2float(h2.x));
                    l2.y = __float2half_rn(oy - __half2float(h2.y));
                    __half* ap = sm + (gcol >> 5) * CHB + lrow * PADK + (gcol & 31);
                    *reinterpret_cast<__half2*>(ap)           = h2;
                    *reinterpret_cast<__half2*>(ap + 4 * CHB) = l2;
                    if (gr < M) {
                        *reinterpret_cast<__half2*>(jb.xh + (size_t)gr * HID + gcol) = h2;
                        *reinterpret_cast<__half2*>(jb.xl + (size_t)gr * HID + gcol) = l2;
                    }
                }
            }
        }
    }
    __syncthreads();   // A tile published

    // ---------------- phase 2: projections (K = 128, 4 chunks) ----------------
    const uint32_t bO = base + 8 * CHB * 2;    // B double-buffer region
    for (int p = 0; p < jb.nproj; ++p) {
        const __half* Bp  = jb.p[p].B;
        const float* bias = jb.p[p].bias;
        float* dst        = jb.p[p].dst;
        const bool two    = (jb.p[p].oneterm == 0);

        #pragma unroll
        for (int mi = 0; mi < 4; ++mi)
            #pragma unroll
            for (int ni = 0; ni < 4; ++ni)
                #pragma unroll
                for (int r = 0; r < 4; ++r) acc[mi][ni][r] = 0.0f;

        auto loadB = [&](int c, int b) {
            const int k0 = c * KC;
            const uint32_t bb = bO + (uint32_t)b * (CHB * 2);
            #pragma unroll
            for (int i = 0; i < 2; ++i) {
                int r = lr + i * 64;
                CPASYNC(bb + (uint32_t)(r * PADK + lk) * 2,
                        Bp + (size_t)r * 128 + k0 + lk, 16);
            }
            asm volatile("cp.async.commit_group;" ::: "memory");
        };

        loadB(0, 0);
        #pragma unroll 1
        for (int c = 0; c < 4; ++c) {
            const int b = c & 1;
            asm volatile("cp.async.wait_group 0;" ::: "memory");
            __syncthreads();
            if (c + 1 < 4) loadB(c + 1, b ^ 1);

            const uint32_t aB = base + (uint32_t)c * (CHB * 2);
            const uint32_t bB = bO + (uint32_t)b * (CHB * 2);
            #pragma unroll
            for (int kk = 0; kk < 2; ++kk) {
                uint32_t ah[4][4], al[4][4], bf2[4][2];
                #pragma unroll
                for (int mi = 0; mi < 4; ++mi) {
                    int row = wm * 64 + mi * 16 + a_row;
                    int col = kk * 16 + a_col;
                    uint32_t off = aB + (uint32_t)(row * PADK + col) * 2;
                    LDSM4(ah[mi][0], ah[mi][1], ah[mi][2], ah[mi][3], off);
                    if (two)
                        LDSM4(al[mi][0], al[mi][1], al[mi][2], al[mi][3],
                              off + 4 * CHB * 2);
                }
                #pragma unroll
                for (int p2 = 0; p2 < 2; ++p2) {
                    int row = wn * 32 + p2 * 16 + b_row;
                    int col = kk * 16 + b_col;
                    uint32_t off = bB + (uint32_t)(row * PADK + col) * 2;
                    LDSM4(bf2[2*p2][0], bf2[2*p2][1], bf2[2*p2+1][0], bf2[2*p2+1][1], off);
                }
                #pragma unroll
                for (int mi = 0; mi < 4; ++mi)
                    #pragma unroll
                    for (int ni = 0; ni < 4; ++ni) {
                        MMA_FP16(acc[mi][ni], ah[mi], bf2[ni]);
                        if (two)
                            MMA_FP16(acc[mi][ni], al[mi], bf2[ni]);
                    }
            }
        }

        // epilogue: fp32 out + bias
        #pragma unroll
        for (int mi = 0; mi < 4; ++mi) {
            #pragma unroll
            for (int ni = 0; ni < 4; ++ni) {
                int gcol = wn * 32 + ni * 8 + c2;
                float2 bb2 = *reinterpret_cast<const float2*>(bias + gcol);
                #pragma unroll
                for (int half = 0; half < 2; ++half) {
                    int gr = m0 + wm * 64 + mi * 16 + r4 + half * 8;
                    if (gr >= M) continue;
                    float2 o;
                    o.x = acc[mi][ni][half * 2 + 0] + bb2.x;
                    o.y = acc[mi][ni][half * 2 + 1] + bb2.y;
                    *reinterpret_cast<float2*>(dst + (size_t)gr * HID + gcol) = o;
                }
            }
        }
    }
}

// ---------------------------------------------------------------------------
// tgemm: generic fp16 split GEMM (used for GEMM3 / GEMM4)
// mode bit0: skip-gate epilogue; bit1: fp16 h/l out; bit2: skip fp32 out;
// bit3: single-term A
// ---------------------------------------------------------------------------
struct GJob { const __half *Ah, *Al, *B;
              const float *bias; float *dst;
              const __half *gxh, *gxl;
              __half *dsth, *dstl;
              int M, K, mode, skipidx, blk0; };
struct GJobs { GJob j[11]; int njobs; };

__global__ __launch_bounds__(256, 2)
void tgemm(GJobs jobs, const float* __restrict__ skipv)
{
    extern __shared__ __half sm[];
    const uint32_t base = smem_u32(sm);
    const int tid = threadIdx.x;
    const int wid = tid >> 5, lane = tid & 31;
    const int wm = wid & 1, wn = wid >> 1;

    int ji = 0;
    #pragma unroll 1
    for (int t = 1; t < jobs.njobs; ++t)
        if ((int)blockIdx.x >= jobs.j[t].blk0) ji = t;
    const GJob jb = jobs.j[ji];
    const int m0 = ((int)blockIdx.x - jb.blk0) * 128;
    const int M = jb.M, K = jb.K;
    const bool twoTerm = !(jb.mode & 8);

    float acc[4][4][4];
    #pragma unroll
    for (int mi = 0; mi < 4; ++mi)
        #pragma unroll
        for (int ni = 0; ni < 4; ++ni)
            #pragma unroll
            for (int r = 0; r < 4; ++r) acc[mi][ni][r] = 0.0f;

    const int a_row = ((lane >> 3) & 1) * 8 + (lane & 7);
    const int a_col = (lane >> 4) * 8;
    const int b_row = (lane >> 4) * 8 + (lane & 7);
    const int b_col = ((lane >> 3) & 1) * 8;
    const int lr = tid >> 2;
    const int lk = (tid & 3) * 8;

    const int kch = (K + KC - 1) / KC;

    auto load_chunk = [&](int c, int b) {
        const int k0 = c * KC;
        const uint32_t bb = base + (uint32_t)b * (3 * CHB * 2);
        #pragma unroll
        for (int i = 0; i < 2; ++i) {
            int r = lr + i * 64;
            int gk = k0 + lk;
            uint32_t off = (uint32_t)(r * PADK + lk) * 2;
            int okA = (m0 + r < M) && (gk < K) ? 16 : 0;
            size_t aoff = okA ? ((size_t)(m0 + r) * K + gk) : 0;
            CPASYNC(bb + off, jb.Ah + aoff, okA);
            if (twoTerm)
                CPASYNC(bb + off + CHB * 2, jb.Al + aoff, okA);
            int okB = (gk < K) ? 16 : 0;
            size_t boff = okB ? ((size_t)r * K + gk) : 0;
            CPASYNC(bb + off + 2 * CHB * 2, jb.B + boff, okB);
        }
        asm volatile("cp.async.commit_group;" ::: "memory");
    };

    load_chunk(0, 0);

    for (int c = 0; c < kch; ++c) {
        const int b = c & 1;
        asm volatile("cp.async.wait_group 0;" ::: "memory");
        __syncthreads();
        if (c + 1 < kch) load_chunk(c + 1, b ^ 1);

        const uint32_t bb = base + (uint32_t)b * (3 * CHB * 2);
        #pragma unroll
        for (int kk = 0; kk < 2; ++kk) {
            uint32_t ah[4][4], al[4][4], bf2[4][2];
            #pragma unroll
            for (int mi = 0; mi < 4; ++mi) {
                int row = wm * 64 + mi * 16 + a_row;
                int col = kk * 16 + a_col;
                uint32_t off = bb + (uint32_t)(row * PADK + col) * 2;
                LDSM4(ah[mi][0], ah[mi][1], ah[mi][2], ah[mi][3], off);
                if (twoTerm)
                    LDSM4(al[mi][0], al[mi][1], al[mi][2], al[mi][3], off + CHB * 2);
            }
            #pragma unroll
            for (int p = 0; p < 2; ++p) {
                int row = wn * 32 + p * 16 + b_row;
                int col = kk * 16 + b_col;
                uint32_t off = bb + 2 * CHB * 2 + (uint32_t)(row * PADK + col) * 2;
                LDSM4(bf2[2*p][0], bf2[2*p][1], bf2[2*p+1][0], bf2[2*p+1][1], off);
            }
            #pragma unroll
            for (int mi = 0; mi < 4; ++mi)
                #pragma unroll
                for (int ni = 0; ni < 4; ++ni) {
                    MMA_FP16(acc[mi][ni], ah[mi], bf2[ni]);
                    if (twoTerm)
                        MMA_FP16(acc[mi][ni], al[mi], bf2[ni]);
                }
        }
    }

    float g = 0.f, hg = 0.f;
    if (jb.mode & 1) {
        g = 1.f / (1.f + expf(-skipv[jb.skipidx]));
        hg = 1.f - g;
    }
    const int r4 = lane >> 2, c2 = (lane & 3) * 2;
    #pragma unroll
    for (int mi = 0; mi < 4; ++mi) {
        #pragma unroll
        for (int ni = 0; ni < 4; ++ni) {
            int gcol = wn * 32 + ni * 8 + c2;
            float2 bb2 = *reinterpret_cast<const float2*>(jb.bias + gcol);
            #pragma unroll
            for (int half = 0; half < 2; ++half) {
                int gr = m0 + wm * 64 + mi * 16 + r4 + half * 8;
                if (gr >= M) continue;
                float2 o;
                o.x = acc[mi][ni][half * 2 + 0] + bb2.x;
                o.y = acc[mi][ni][half * 2 + 1] + bb2.y;
                if (jb.mode & 1) {
                    __half2 xh2 = *reinterpret_cast<const __half2*>(
                        jb.gxh + (size_t)gr * HID + gcol);
                    __half2 xl2 = *reinterpret_cast<const __half2*>(
                        jb.gxl + (size_t)gr * HID + gcol);
                    float xx = __half2float(xh2.x) + __half2float(xl2.x);
                    float xy = __half2float(xh2.y) + __half2float(xl2.y);
                    o.x = fmaxf(0.f, g * o.x + hg * xx);
                    o.y = fmaxf(0.f, g * o.y + hg * xy);
                }
                if (!(jb.mode & 4))
                    *reinterpret_cast<float2*>(jb.dst + (size_t)gr * HID + gcol) = o;
                if (jb.mode & 2) {
                    __half2 h2, l2;
                    h2.x = __float2half_rn(o.x);
                    h2.y = __float2half_rn(o.y);
                    l2.x = __float2half_rn(o.x - __half2float(h2.x));
                    l2.y = __float2half_rn(o.y - __half2float(h2.y));
                    *reinterpret_cast<__half2*>(jb.dsth + (size_t)gr * HID + gcol) = h2;
                    *reinterpret_cast<__half2*>(jb.dstl + (size_t)gr * HID + gcol) = l2;
                }
            }
        }
    }
}

// ---------------------------------------------------------------------------
static inline int cdiv(int a, int b) { return (a + b - 1) / b; }

extern "C" void kernel_launch(void* const* d_in, const int* in_sizes, int n_in,
                              void* d_out, int out_size)
{
    const float* x_herb = (const float*)d_in[0];
    const float* x_ing  = (const float*)d_in[1];
    const float* x_tgt  = (const float*)d_in[2];
    const float* W_herb = (const float*)d_in[3];
    const float* b_herb = (const float*)d_in[4];
    const float* W_ing  = (const float*)d_in[5];
    const float* b_ing  = (const float*)d_in[6];
    const float* W_tgt  = (const float*)d_in[7];
    const float* b_tgt  = (const float*)d_in[8];
    const float* Wk     = (const float*)d_in[9];
    const float* bk     = (const float*)d_in[10];
    const float* Wq     = (const float*)d_in[11];
    const float* bq     = (const float*)d_in[12];
    const float* Wv     = (const float*)d_in[13];
    const float* bv     = (const float*)d_in[14];
    const float* a_rel  = (const float*)d_in[15];
    const float* m_rel  = (const float*)d_in[16];
    const float* p_rel  = (const float*)d_in[17];
    const float* Wa     = (const float*)d_in[18];
    const float* ba     = (const float*)d_in[19];
    const float* skip   = (const float*)d_in[20];
    const float* W_out  = (const float*)d_in[21];
    const float* b_out  = (const float*)d_in[22];
    const int* src_e[4] = { (const int*)d_in[23], (const int*)d_in[25],
                            (const int*)d_in[27], (const int*)d_in[29] };
    const int* dst_e[4] = { (const int*)d_in[24], (const int*)d_in[26],
                            (const int*)d_in[28], (const int*)d_in[30] };

    const int Nh = in_sizes[0] / 400;
    const int Ni = in_sizes[1] / 300;
    const int Nt = in_sizes[2] / 200;
    const int NN = Nh + Ni + Nt;
    int E[4] = { in_sizes[23], in_sizes[25], in_sizes[27], in_sizes[29] };

    float *q, *krel, *vrel, *bfp;
    cudaGetSymbolAddress((void**)&q, g_q);
    cudaGetSymbolAddress((void**)&krel, g_krel);
    cudaGetSymbolAddress((void**)&vrel, g_vrel);
    cudaGetSymbolAddress((void**)&bfp, g_bf);

    int *deg, *rowptr, *pos, *erec, *bsum;
    cudaGetSymbolAddress((void**)&deg, g_deg);
    cudaGetSymbolAddress((void**)&rowptr, g_rowptr);
    cudaGetSymbolAddress((void**)&pos, g_pos);
    cudaGetSymbolAddress((void**)&erec, g_erec);
    cudaGetSymbolAddress((void**)&bsum, g_bsum);

    __half *xih, *xil, *xsh, *xsl, *gbh, *gbl, *hth, *htl, *wth;
    cudaGetSymbolAddress((void**)&xih, g_xih);
    cudaGetSymbolAddress((void**)&xil, g_xil);
    cudaGetSymbolAddress((void**)&xsh, g_xsh);
    cudaGetSymbolAddress((void**)&xsl, g_xsl);
    cudaGetSymbolAddress((void**)&gbh, g_gbh);
    cudaGetSymbolAddress((void**)&gbl, g_gbl);
    cudaGetSymbolAddress((void**)&hth, g_hth);
    cudaGetSymbolAddress((void**)&htl, g_htl);
    cudaGetSymbolAddress((void**)&wth, g_wth);

    cudaFuncSetAttribute(tgemm, cudaFuncAttributeMaxDynamicSharedMemorySize, TG_SMEM);
    cudaFuncSetAttribute(projchain, cudaFuncAttributeMaxDynamicSharedMemorySize, PC_SMEM);

    static cudaStream_t sB = nullptr, sC = nullptr;
    static cudaEvent_t evRoot = nullptr, evC = nullptr, ev2a = nullptr,
                       ev2b = nullptr, evAH = nullptr, evG3 = nullptr;
    if (sB == nullptr) {
        cudaStreamCreateWithFlags(&sB, cudaStreamNonBlocking);
        cudaStreamCreateWithFlags(&sC, cudaStreamNonBlocking);
        cudaEventCreateWithFlags(&evRoot, cudaEventDisableTiming);
        cudaEventCreateWithFlags(&evC, cudaEventDisableTiming);
        cudaEventCreateWithFlags(&ev2a, cudaEventDisableTiming);
        cudaEventCreateWithFlags(&ev2b, cudaEventDisableTiming);
        cudaEventCreateWithFlags(&evAH, cudaEventDisableTiming);
        cudaEventCreateWithFlags(&evG3, cudaEventDisableTiming);
    }

    const int offT3[3]   = { 0, Nh, Nh + Ni };
    const int slotOff[4] = { 0, Nh, Nh + Ni, Nh + 2 * Ni };
    const int dstOff[4]  = { Nh, 0, Nh + Ni, Nh };
    const int Ntype[3]   = { Nh, Ni, Nt };

    EArr ea;
    for (int e = 0; e < 4; ++e) {
        ea.src[e] = src_e[e]; ea.dst[e] = dst_e[e];
        ea.E[e] = E[e]; ea.base[e] = dstOff[e]; ea.slot[e] = slotOff[e];
    }

    // fork
    cudaEventRecord(evRoot, 0);
    cudaStreamWaitEvent(sB, evRoot, 0);
    cudaStreamWaitEvent(sC, evRoot, 0);

    // ---- stream B: CSR build
    zero_deg<<<cdiv(NN, 256), 256, 0, sB>>>(deg, NN);
    hist_deg<<<dim3(128, 4), 256, 0, sB>>>(ea, deg);
    const int NB = cdiv(NN, 256);
    scan1<<<NB, 256, 0, sB>>>(deg, rowptr, bsum, NN);
    scan2<<<1, 512, 0, sB>>>(bsum, NB);
    scan3<<<NB, 256, 0, sB>>>(deg, rowptr, bsum, pos, NN);
    scatter_edges<<<dim3(128, 4), 256, 0, sB>>>(ea, pos, erec);

    // ---- stream C: input converts + weight transposes
    const size_t xiI = (size_t)Nh * KH;
    const size_t xiT = xiI + (size_t)Ni * KI;
    convert_pad4<<<cdiv(Nh * KH / 4, 256), 256, 0, sC>>>(x_herb, xih,       xil,       Nh, 400, KH);
    convert_pad4<<<cdiv(Ni * KI / 4, 256), 256, 0, sC>>>(x_ing,  xih + xiI, xil + xiI, Ni, 300, KI);
    convert_pad4<<<cdiv(Nt * KT / 4, 256), 256, 0, sC>>>(x_tgt,  xih + xiT, xil + xiT, Nt, 200, KT);
    {
        TJobs T{};
        int t = 0;
        T.j[t++] = { W_herb, wth + WH_OFF, 400, KH };
        T.j[t++] = { W_ing,  wth + WI_OFF, 300, KI };
        T.j[t++] = { W_tgt,  wth + WT_OFF, 200, KT };
        for (int i = 0; i < 3; ++i)
            T.j[t++] = { Wq + (size_t)i*HID*HID, wth + WQ_OFF + i*16384, 128, 128 };
        for (int i = 0; i < 3; ++i)
            T.j[t++] = { Wa + (size_t)i*HID*HID, wth + WA_OFF + i*16384, 128, 128 };
        T.j[t++] = { W_out, wth + WO_OFF, 128, 128 };
        transpose_wt<<<dim3(64, 10), 256, 0, sC>>>(T);
    }
    cudaEventRecord(evC, sC);

    // ---- main stream: fuse then the fused projection chain
    fuse_rel_weights<<<8, 256>>>(Wk, bk, Wv, bv, a_rel, m_rel, p_rel, wth, bfp);
    cudaStreamWaitEvent(0, evC, 0);

    // L1: herb + ing (produces q_herb, kr0/vr0, q_ing, kr1/vr1, kr2/vr2 + xs h/l)
    {
        PJobs J{};
        J.njobs = 2;
        PJob& h = J.j[0];
        h.Ah = xih; h.Al = xil; h.Bin = wth + WH_OFF; h.bias_in = b_herb;
        h.xh = xsh; h.xl = xsl; h.M = Nh; h.Kin = KH; h.nproj = 3; h.blk0 = 0;
        h.p[0] = { wth + WQ_OFF,           bq,          q,                             0 };
        h.p[1] = { wth + WF_OFF + 0*16384, bfp + 0*HID, krel + (size_t)slotOff[0]*HID, 1 };
        h.p[2] = { wth + WF_OFF + 1*16384, bfp + 1*HID, vrel + (size_t)slotOff[0]*HID, 1 };
        PJob& g2 = J.j[1];
        g2.Ah = xih + xiI; g2.Al = xil + xiI; g2.Bin = wth + WI_OFF; g2.bias_in = b_ing;
        g2.xh = xsh + (size_t)Nh*HID; g2.xl = xsl + (size_t)Nh*HID;
        g2.M = Ni; g2.Kin = KI; g2.nproj = 5; g2.blk0 = cdiv(Nh, 128);
        g2.p[0] = { wth + WQ_OFF + 1*16384, bq + 1*HID,  q + (size_t)Nh*HID,            0 };
        g2.p[1] = { wth + WF_OFF + 2*16384, bfp + 2*HID, krel + (size_t)slotOff[1]*HID, 1 };
        g2.p[2] = { wth + WF_OFF + 3*16384, bfp + 3*HID, vrel + (size_t)slotOff[1]*HID, 1 };
        g2.p[3] = { wth + WF_OFF + 4*16384, bfp + 4*HID, krel + (size_t)slotOff[2]*HID, 1 };
        g2.p[4] = { wth + WF_OFF + 5*16384, bfp + 5*HID, vrel + (size_t)slotOff[2]*HID, 1 };
        projchain<<<cdiv(Nh, 128) + cdiv(Ni, 128), 256, PC_SMEM>>>(J);
    }
    cudaEventRecord(ev2a, 0);

    // L2: tgt (q_tgt, kr3/vr3 + xs h/l)
    {
        PJobs J{};
        J.njobs = 1;
        PJob& t = J.j[0];
        t.Ah = xih + xiT; t.Al = xil + xiT; t.Bin = wth + WT_OFF; t.bias_in = b_tgt;
        t.xh = xsh + (size_t)(Nh+Ni)*HID; t.xl = xsl + (size_t)(Nh+Ni)*HID;
        t.M = Nt; t.Kin = KT; t.nproj = 3; t.blk0 = 0;
        t.p[0] = { wth + WQ_OFF + 2*16384, bq + 2*HID,  q + (size_t)(Nh+Ni)*HID,       0 };
        t.p[1] = { wth + WF_OFF + 6*16384, bfp + 6*HID, krel + (size_t)slotOff[3]*HID, 1 };
        t.p[2] = { wth + WF_OFF + 7*16384, bfp + 7*HID, vrel + (size_t)slotOff[3]*HID, 1 };
        projchain<<<cdiv(Nt, 128), 256, PC_SMEM>>>(J);
    }
    cudaEventRecord(ev2b, 0);

    // ---- stream B: herb attend, then rest + GEMM3 ing/tgt
    float* outp = (float*)d_out;
    cudaStreamWaitEvent(sB, ev2a, 0);
    attend<<<cdiv(Nh * 32, 256), 256, 0, sB>>>(rowptr, erec, q, krel, vrel,
                                               gbh, gbl, 0, Nh);
    cudaEventRecord(evAH, sB);
    cudaStreamWaitEvent(sB, ev2b, 0);
    attend<<<cdiv((NN - Nh) * 32, 256), 256, 0, sB>>>(rowptr, erec, q, krel, vrel,
                                                      gbh, gbl, Nh, NN);
    {   // GEMM3 ing + tgt -> d_out directly (2-term)
        GJobs J{}; int nb = 0;
        for (int i = 1; i < 3; ++i) {
            float* d = (i == 1) ? outp + (size_t)Nh*HID : outp + (size_t)(Nh+Ni)*HID;
            J.j[J.njobs] = { gbh + (size_t)offT3[i]*HID, gbl + (size_t)offT3[i]*HID,
                             wth + WA_OFF + i*16384, ba + i*HID, d,
                             xsh + (size_t)offT3[i]*HID, xsl + (size_t)offT3[i]*HID,
                             nullptr, nullptr, Ntype[i], 128, 1, i, nb };
            J.njobs++; nb += cdiv(Ntype[i], 128);
        }
        tgemm<<<nb, 256, TG_SMEM, sB>>>(J, skip);
    }
    cudaEventRecord(evG3, sB);

    // ---- main: herb output chain
    cudaStreamWaitEvent(0, evAH, 0);
    {   // GEMM3 herb -> hth/htl (fp16 h/l only, 2-term)
        GJobs J{};
        J.j[0] = { gbh, gbl, wth + WA_OFF, ba, nullptr,
                   xsh, xsl, hth, htl, Nh, 128, 1 | 2 | 4, 0, 0 };
        J.njobs = 1;
        tgemm<<<cdiv(Nh, 128), 256, TG_SMEM>>>(J, skip);
    }
    cudaStreamWaitEvent(0, evG3, 0);
    {   // GEMM4: final herb linear (2-term)
        GJobs J{};
        J.j[0] = { hth, htl, wth + WO_OFF, b_out, outp,
                   nullptr, nullptr, nullptr, nullptr, Nh, 128, 0, 0, 0 };
        J.njobs = 1;
        tgemm<<<cdiv(Nh, 128), 256, TG_SMEM>>>(J, skip);
    }
}

// round 15
// speedup vs baseline: 1.0809x; 1.0809x over previous
#include <cuda_runtime.h>
#include <cuda_fp16.h>
#include <cstdint>
#include <math.h>

// ---------------------------------------------------------------------------
// Problem constants
// ---------------------------------------------------------------------------
#define HID 128
#define NHEAD 8
#define HDIM 16

#define NH_MAX 8000
#define NI_MAX 40000
#define NT_MAX 20000
#define NN_MAX (NH_MAX + NI_MAX + NT_MAX)
#define NREL_MAX (NH_MAX + 2*NI_MAX + NT_MAX)
#define MAXE 250000

#define KH 400
#define KI 304
#define KT 200
#define XI_TOTAL ((size_t)NH_MAX*KH + (size_t)NI_MAX*KI + (size_t)NT_MAX*KT)

// fp16 weight pool offsets (transposed [128][Kp])
#define WH_OFF 0
#define WI_OFF 51200
#define WT_OFF 90112
#define WQ_OFF 115712
#define WF_OFF 164864
#define WA_OFF 295936
#define WO_OFF 345088
#define WPOOL  361472

// ---------------------------------------------------------------------------
// Device scratch
// ---------------------------------------------------------------------------
__device__ float g_q    [(size_t)NN_MAX   * HID];
__device__ float g_krel [(size_t)NREL_MAX * HID];
__device__ float g_vrel [(size_t)NREL_MAX * HID];
__device__ float g_bf   [8 * HID];

__device__ int g_deg   [NN_MAX];
__device__ int g_rowptr[NN_MAX + 1];
__device__ int g_pos   [NN_MAX];
__device__ int g_erec  [4 * MAXE];
__device__ int g_bsum  [512];

__device__ __half g_xih[XI_TOTAL];
__device__ __half g_xil[XI_TOTAL];
__device__ __half g_xsh[(size_t)NN_MAX * HID];
__device__ __half g_xsl[(size_t)NN_MAX * HID];
__device__ __half g_gbh[(size_t)NN_MAX * HID];
__device__ __half g_gbl[(size_t)NN_MAX * HID];
__device__ __half g_hth[(size_t)NH_MAX * HID];
__device__ __half g_htl[(size_t)NH_MAX * HID];
__device__ __half g_wth[WPOOL];

// ---------------------------------------------------------------------------
// Fuse Wk/Wv with relation matrices; p_rel/sqrtD folded into k-kind.
// Writes TRANSPOSED fp16 into the weight pool.
// ---------------------------------------------------------------------------
__global__ void fuse_rel_weights(const float* __restrict__ Wk, const float* __restrict__ bk,
                                 const float* __restrict__ Wv, const float* __restrict__ bv,
                                 const float* __restrict__ a_rel, const float* __restrict__ m_rel,
                                 const float* __restrict__ prel,
                                 __half* __restrict__ wth, float* __restrict__ bf)
{
    int slot = blockIdx.x;
    int e = slot >> 1, kind = slot & 1;
    int s = (e == 0) ? 0 : ((e == 3) ? 2 : 1);
    const float* Wb = (kind ? Wv : Wk) + (size_t)s * HID * HID;
    const float* bb = (kind ? bv : bk) + (size_t)s * HID;
    const float* rel = (kind ? m_rel : a_rel) + (size_t)e * NHEAD * HDIM * HDIM;

    for (int idx = threadIdx.x; idx < HID * HID; idx += blockDim.x) {
        int i = idx >> 7, j = idx & 127;
        int h = j >> 4, j16 = j & 15;
        float acc = 0.0f;
        #pragma unroll
        for (int d = 0; d < HDIM; ++d)
            acc += Wb[i * HID + h * HDIM + d] * rel[(h * HDIM + d) * HDIM + j16];
        if (kind == 0) acc *= prel[e * NHEAD + h] * 0.25f;
        wth[(size_t)WF_OFF + (size_t)slot * 16384 + j * 128 + i] = __float2half_rn(acc);
    }
    for (int j = threadIdx.x; j < HID; j += blockDim.x) {
        int h = j >> 4, j16 = j & 15;
        float acc = 0.0f;
        #pragma unroll
        for (int d = 0; d < HDIM; ++d)
            acc += bb[h * HDIM + d] * rel[(h * HDIM + d) * HDIM + j16];
        if (kind == 0) acc *= prel[e * NHEAD + h] * 0.25f;
        bf[slot * HID + j] = acc;
    }
}

// ---------------------------------------------------------------------------
// fp32 -> fp16 hi/lo, vectorized, with K padding
// ---------------------------------------------------------------------------
__global__ void convert_pad4(const float* __restrict__ src,
                             __half* __restrict__ dh, __half* __restrict__ dl,
                             int M, int K, int Kp)
{
    int idx4 = blockIdx.x * blockDim.x + threadIdx.x;
    int kq = Kp >> 2;
    if (idx4 >= M * kq) return;
    int r = idx4 / kq, k4 = (idx4 - r * kq) << 2;
    float4 v = make_float4(0.f, 0.f, 0.f, 0.f);
    if (k4 < K)
        v = *reinterpret_cast<const float4*>(src + (size_t)r * K + k4);
    __half2 h01, h23, l01, l23;
    h01.x = __float2half_rn(v.x); h01.y = __float2half_rn(v.y);
    h23.x = __float2half_rn(v.z); h23.y = __float2half_rn(v.w);
    l01.x = __float2half_rn(v.x - __half2float(h01.x));
    l01.y = __float2half_rn(v.y - __half2float(h01.y));
    l23.x = __float2half_rn(v.z - __half2float(h23.x));
    l23.y = __float2half_rn(v.w - __half2float(h23.y));
    *reinterpret_cast<__half2*>(dh + (size_t)idx4 * 4)     = h01;
    *reinterpret_cast<__half2*>(dh + (size_t)idx4 * 4 + 2) = h23;
    *reinterpret_cast<__half2*>(dl + (size_t)idx4 * 4)     = l01;
    *reinterpret_cast<__half2*>(dl + (size_t)idx4 * 4 + 2) = l23;
}

// ---------------------------------------------------------------------------
// Weight transpose + fp16
// ---------------------------------------------------------------------------
struct TJob { const float* W; __half* th; int K; int Kp; };
struct TJobs { TJob j[10]; };

__global__ void transpose_wt(TJobs jobs)
{
    TJob jb = jobs.j[blockIdx.y];
    int total = 128 * jb.Kp;
    for (int idx = blockIdx.x * blockDim.x + threadIdx.x; idx < total;
         idx += gridDim.x * blockDim.x) {
        int n = idx / jb.Kp, k = idx - n * jb.Kp;
        float v = (k < jb.K) ? jb.W[(size_t)k * 128 + n] : 0.0f;
        jb.th[idx] = __float2half_rn(v);
    }
}

// ---------------------------------------------------------------------------
// CSR build
// ---------------------------------------------------------------------------
struct EArr { const int* src[4]; const int* dst[4]; int E[4]; int base[4]; int slot[4]; };

__global__ void zero_deg(int* __restrict__ deg, int NN)
{
    int i = blockIdx.x * blockDim.x + threadIdx.x;
    if (i < NN) deg[i] = 0;
}

__global__ void hist_deg(EArr ea, int* __restrict__ deg)
{
    int e = blockIdx.y;
    const int* dst = ea.dst[e];
    int E = ea.E[e], base = ea.base[e];
    for (int i = blockIdx.x * blockDim.x + threadIdx.x; i < E;
         i += gridDim.x * blockDim.x)
        atomicAdd(&deg[base + dst[i]], 1);
}

__global__ void scan1(const int* __restrict__ deg, int* __restrict__ rowptr,
                      int* __restrict__ bsum, int NN)
{
    __shared__ int ws[8];
    int i = blockIdx.x * 256 + threadIdx.x;
    int lane = threadIdx.x & 31, w = threadIdx.x >> 5;
    int x = (i < NN) ? deg[i] : 0;
    #pragma unroll
    for (int o = 1; o < 32; o <<= 1) {
        int y = __shfl_up_sync(0xffffffffu, x, o);
        if (lane >= o) x += y;
    }
    if (lane == 31) ws[w] = x;
    __syncthreads();
    if (threadIdx.x < 8) {
        int y = ws[threadIdx.x];
        #pragma unroll
        for (int o = 1; o < 8; o <<= 1) {
            int z = __shfl_up_sync(0xffu, y, o);
            if ((int)threadIdx.x >= o) y += z;
        }
        ws[threadIdx.x] = y;
    }
    __syncthreads();
    if (w > 0) x += ws[w - 1];
    if (i < NN) rowptr[i + 1] = x;
    if (threadIdx.x == 255) bsum[blockIdx.x] = x;
}

__global__ void scan2(int* __restrict__ bsum, int NB)
{
    __shared__ int s[512];
    int t = threadIdx.x;
    int orig = (t < NB) ? bsum[t] : 0;
    s[t] = orig;
    __syncthreads();
    for (int o = 1; o < 512; o <<= 1) {
        int v = (t >= o) ? s[t - o] : 0;
        __syncthreads();
        s[t] += v;
        __syncthreads();
    }
    if (t < NB) bsum[t] = s[t] - orig;
}

__global__ void scan3(const int* __restrict__ deg, int* __restrict__ rowptr,
                      const int* __restrict__ bsum, int* __restrict__ pos, int NN)
{
    int i = blockIdx.x * 256 + threadIdx.x;
    if (i >= NN) return;
    int val = rowptr[i + 1] + bsum[blockIdx.x];
    rowptr[i + 1] = val;
    pos[i] = val - deg[i];
    if (i == 0) rowptr[0] = 0;
}

__global__ void scatter_edges(EArr ea, int* __restrict__ pos, int* __restrict__ erec)
{
    int e = blockIdx.y;
    const int* src = ea.src[e];
    const int* dst = ea.dst[e];
    int E = ea.E[e], base = ea.base[e], slot = ea.slot[e];
    for (int i = blockIdx.x * blockDim.x + threadIdx.x; i < E;
         i += gridDim.x * blockDim.x) {
        int p = atomicAdd(&pos[base + dst[i]], 1);
        erec[p] = slot + src[i];
    }
}

// ---------------------------------------------------------------------------
// Fused attention (no running max — logits sigma~1 by construction, overflow
// needs 25+ sigma). One warp per dst node. Writes gelu(agg/den) fp16 h/l.
// ---------------------------------------------------------------------------
__global__ __launch_bounds__(256)
void attend(const int* __restrict__ rowptr, const int* __restrict__ erec,
            const float* __restrict__ q, const float* __restrict__ krel,
            const float* __restrict__ vrel,
            __half* __restrict__ oh, __half* __restrict__ ol,
            int n0, int n1)
{
    const int n = n0 + ((blockIdx.x * blockDim.x + threadIdx.x) >> 5);
    const int lane = threadIdx.x & 31;
    if (n >= n1) return;

    const int lo = rowptr[n], hi = rowptr[n + 1];
    const float4 qv = *reinterpret_cast<const float4*>(q + (size_t)n * HID + lane * 4);

    float den = 0.0f;
    float4 acc = make_float4(0.f, 0.f, 0.f, 0.f);

    float4 k0, v0, k1, v1;
    if (lo < hi) {
        int ss = __ldg(erec + lo);
        k0 = *reinterpret_cast<const float4*>(krel + (size_t)ss * HID + lane * 4);
        v0 = *reinterpret_cast<const float4*>(vrel + (size_t)ss * HID + lane * 4);
    }
    if (lo + 1 < hi) {
        int ss = __ldg(erec + lo + 1);
        k1 = *reinterpret_cast<const float4*>(krel + (size_t)ss * HID + lane * 4);
        v1 = *reinterpret_cast<const float4*>(vrel + (size_t)ss * HID + lane * 4);
    }
    for (int i = lo; i < hi; ++i) {
        float4 kv = k0, vv = v0;
        k0 = k1; v0 = v1;
        if (i + 2 < hi) {
            int ss = __ldg(erec + i + 2);
            k1 = *reinterpret_cast<const float4*>(krel + (size_t)ss * HID + lane * 4);
            v1 = *reinterpret_cast<const float4*>(vrel + (size_t)ss * HID + lane * 4);
        }
        float p = qv.x * kv.x + qv.y * kv.y + qv.z * kv.z + qv.w * kv.w;
        p += __shfl_xor_sync(0xffffffffu, p, 1);
        p += __shfl_xor_sync(0xffffffffu, p, 2);
        float ex = __expf(p);
        den += ex;
        acc.x = fmaf(ex, vv.x, acc.x);
        acc.y = fmaf(ex, vv.y, acc.y);
        acc.z = fmaf(ex, vv.z, acc.z);
        acc.w = fmaf(ex, vv.w, acc.w);
    }

    const float inv = 1.0f / (den + 1e-16f);
    float o[4] = { acc.x * inv, acc.y * inv, acc.z * inv, acc.w * inv };
    #pragma unroll
    for (int j = 0; j < 4; ++j)
        o[j] = 0.5f * o[j] * (1.0f + erff(o[j] * 0.70710678118654752f));
    __half2 h01, h23, l01, l23;
    h01.x = __float2half_rn(o[0]); h01.y = __float2half_rn(o[1]);
    h23.x = __float2half_rn(o[2]); h23.y = __float2half_rn(o[3]);
    l01.x = __float2half_rn(o[0] - __half2float(h01.x));
    l01.y = __float2half_rn(o[1] - __half2float(h01.y));
    l23.x = __float2half_rn(o[2] - __half2float(h23.x));
    l23.y = __float2half_rn(o[3] - __half2float(h23.y));
    size_t ob = (size_t)n * HID + lane * 4;
    *reinterpret_cast<__half2*>(oh + ob)     = h01;
    *reinterpret_cast<__half2*>(oh + ob + 2) = h23;
    *reinterpret_cast<__half2*>(ol + ob)     = l01;
    *reinterpret_cast<__half2*>(ol + ob + 2) = l23;
}

// ---------------------------------------------------------------------------
// fp16 split-precision tensor-core GEMM, 3-stage cp.async pipeline.
// 2-term: D = (Ah + Al) @ B ; 1-term (mode bit3): D = Ah @ B
// mode bit0: skip-gate epilogue; bit1: fp16 h/l out; bit2: skip fp32 out;
// bit3: single-term A
// ---------------------------------------------------------------------------
#define KC 32
#define PADK 40
#define CHB (128 * PADK)
#define NSTG 3
#define TG_SMEM (NSTG * 3 * CHB * 2)      // 3 stages x 3 arrays (ah, al, b)

struct GJob { const __half *Ah, *Al, *B;
              const float *bias; float *dst;
              const __half *gxh, *gxl;
              __half *dsth, *dstl;
              int M, K, mode, skipidx, blk0; };
struct GJobs { GJob j[11]; int njobs; };

__device__ __forceinline__ uint32_t smem_u32(const void* p) {
    uint32_t a;
    asm("{ .reg .u64 t; cvta.to.shared.u64 t, %1; cvt.u32.u64 %0, t; }" : "=r"(a) : "l"(p));
    return a;
}

#define CPASYNC(dst, src, sz)                                                 \
    asm volatile("cp.async.ca.shared.global [%0], [%1], 16, %2;"              \
        :: "r"(dst), "l"(src), "r"(sz))

#define LDSM4(r0, r1, r2, r3, addr)                                           \
    asm volatile("ldmatrix.sync.aligned.m8n8.x4.shared.b16 {%0,%1,%2,%3}, [%4];" \
        : "=r"(r0), "=r"(r1), "=r"(r2), "=r"(r3) : "r"(addr))

#define MMA_FP16(d, a, b)                                                     \
    asm volatile("mma.sync.aligned.m16n8k16.row.col.f32.f16.f16.f32 "         \
        "{%0,%1,%2,%3}, {%4,%5,%6,%7}, {%8,%9}, {%0,%1,%2,%3};"               \
        : "+f"((d)[0]), "+f"((d)[1]), "+f"((d)[2]), "+f"((d)[3])              \
        : "r"((a)[0]), "r"((a)[1]), "r"((a)[2]), "r"((a)[3]),                 \
          "r"((b)[0]), "r"((b)[1]))

__global__ __launch_bounds__(256, 2)
void tgemm(GJobs jobs, const float* __restrict__ skipv)
{
    extern __shared__ __half sm[];
    const uint32_t base = smem_u32(sm);
    const int tid = threadIdx.x;
    const int wid = tid >> 5, lane = tid & 31;
    const int wm = wid & 1, wn = wid >> 1;

    int ji = 0;
    #pragma unroll 1
    for (int t = 1; t < jobs.njobs; ++t)
        if ((int)blockIdx.x >= jobs.j[t].blk0) ji = t;
    const GJob jb = jobs.j[ji];
    const int m0 = ((int)blockIdx.x - jb.blk0) * 128;
    const int M = jb.M, K = jb.K;
    const bool twoTerm = !(jb.mode & 8);

    float acc[4][4][4];
    #pragma unroll
    for (int mi = 0; mi < 4; ++mi)
        #pragma unroll
        for (int ni = 0; ni < 4; ++ni)
            #pragma unroll
            for (int r = 0; r < 4; ++r) acc[mi][ni][r] = 0.0f;

    const int a_row = ((lane >> 3) & 1) * 8 + (lane & 7);
    const int a_col = (lane >> 4) * 8;
    const int b_row = (lane >> 4) * 8 + (lane & 7);
    const int b_col = ((lane >> 3) & 1) * 8;
    const int lr = tid >> 2;
    const int lk = (tid & 3) * 8;

    const int kch = (K + KC - 1) / KC;

    auto load_chunk = [&](int c) {
        const int k0 = c * KC;
        const uint32_t bb = base + (uint32_t)(c % NSTG) * (3 * CHB * 2);
        #pragma unroll
        for (int i = 0; i < 2; ++i) {
            int r = lr + i * 64;
            int gk = k0 + lk;
            uint32_t off = (uint32_t)(r * PADK + lk) * 2;
            int okA = (m0 + r < M) && (gk < K) ? 16 : 0;
            size_t aoff = okA ? ((size_t)(m0 + r) * K + gk) : 0;
            CPASYNC(bb + off, jb.Ah + aoff, okA);
            if (twoTerm)
                CPASYNC(bb + off + CHB * 2, jb.Al + aoff, okA);
            int okB = (gk < K) ? 16 : 0;
            size_t boff = okB ? ((size_t)r * K + gk) : 0;
            CPASYNC(bb + off + 2 * CHB * 2, jb.B + boff, okB);
        }
        asm volatile("cp.async.commit_group;" ::: "memory");
    };

    // prologue: 2 chunks in flight
    load_chunk(0);
    if (kch > 1) load_chunk(1);

    for (int c = 0; c < kch; ++c) {
        // chunk c must be complete; chunk c+1 may stay in flight
        if (c + 1 < kch)
            asm volatile("cp.async.wait_group 1;" ::: "memory");
        else
            asm volatile("cp.async.wait_group 0;" ::: "memory");
        // single barrier: publishes buf c AND orders all warps' compute of
        // chunk c-1 before the load of c+2 overwrites buf (c+2)%3 == (c-1)%3
        __syncthreads();
        if (c + 2 < kch) load_chunk(c + 2);

        const uint32_t bb = base + (uint32_t)(c % NSTG) * (3 * CHB * 2);
        #pragma unroll
        for (int kk = 0; kk < 2; ++kk) {
            uint32_t ah[4][4], al[4][4], bf2[4][2];
            #pragma unroll
            for (int mi = 0; mi < 4; ++mi) {
                int row = wm * 64 + mi * 16 + a_row;
                int col = kk * 16 + a_col;
                uint32_t off = bb + (uint32_t)(row * PADK + col) * 2;
                LDSM4(ah[mi][0], ah[mi][1], ah[mi][2], ah[mi][3], off);
                if (twoTerm)
                    LDSM4(al[mi][0], al[mi][1], al[mi][2], al[mi][3], off + CHB * 2);
            }
            #pragma unroll
            for (int p = 0; p < 2; ++p) {
                int row = wn * 32 + p * 16 + b_row;
                int col = kk * 16 + b_col;
                uint32_t off = bb + 2 * CHB * 2 + (uint32_t)(row * PADK + col) * 2;
                LDSM4(bf2[2*p][0], bf2[2*p][1], bf2[2*p+1][0], bf2[2*p+1][1], off);
            }
            #pragma unroll
            for (int mi = 0; mi < 4; ++mi)
                #pragma unroll
                for (int ni = 0; ni < 4; ++ni) {
                    MMA_FP16(acc[mi][ni], ah[mi], bf2[ni]);
                    if (twoTerm)
                        MMA_FP16(acc[mi][ni], al[mi], bf2[ni]);
                }
        }
    }

    float g = 0.f, hg = 0.f;
    if (jb.mode & 1) {
        g = 1.f / (1.f + expf(-skipv[jb.skipidx]));
        hg = 1.f - g;
    }
    const int r4 = lane >> 2, c2 = (lane & 3) * 2;
    #pragma unroll
    for (int mi = 0; mi < 4; ++mi) {
        #pragma unroll
        for (int ni = 0; ni < 4; ++ni) {
            int gcol = wn * 32 + ni * 8 + c2;
            float2 bb2 = *reinterpret_cast<const float2*>(jb.bias + gcol);
            #pragma unroll
            for (int half = 0; half < 2; ++half) {
                int gr = m0 + wm * 64 + mi * 16 + r4 + half * 8;
                if (gr >= M) continue;
                float2 o;
                o.x = acc[mi][ni][half * 2 + 0] + bb2.x;
                o.y = acc[mi][ni][half * 2 + 1] + bb2.y;
                if (jb.mode & 1) {
                    __half2 xh2 = *reinterpret_cast<const __half2*>(
                        jb.gxh + (size_t)gr * HID + gcol);
                    __half2 xl2 = *reinterpret_cast<const __half2*>(
                        jb.gxl + (size_t)gr * HID + gcol);
                    float xx = __half2float(xh2.x) + __half2float(xl2.x);
                    float xy = __half2float(xh2.y) + __half2float(xl2.y);
                    o.x = fmaxf(0.f, g * o.x + hg * xx);
                    o.y = fmaxf(0.f, g * o.y + hg * xy);
                }
                if (!(jb.mode & 4))
                    *reinterpret_cast<float2*>(jb.dst + (size_t)gr * HID + gcol) = o;
                if (jb.mode & 2) {
                    __half2 h2, l2;
                    h2.x = __float2half_rn(o.x);
                    h2.y = __float2half_rn(o.y);
                    l2.x = __float2half_rn(o.x - __half2float(h2.x));
                    l2.y = __float2half_rn(o.y - __half2float(h2.y));
                    *reinterpret_cast<__half2*>(jb.dsth + (size_t)gr * HID + gcol) = h2;
                    *reinterpret_cast<__half2*>(jb.dstl + (size_t)gr * HID + gcol) = l2;
                }
            }
        }
    }
}

// ---------------------------------------------------------------------------
static inline int cdiv(int a, int b) { return (a + b - 1) / b; }

extern "C" void kernel_launch(void* const* d_in, const int* in_sizes, int n_in,
                              void* d_out, int out_size)
{
    const float* x_herb = (const float*)d_in[0];
    const float* x_ing  = (const float*)d_in[1];
    const float* x_tgt  = (const float*)d_in[2];
    const float* W_herb = (const float*)d_in[3];
    const float* b_herb = (const float*)d_in[4];
    const float* W_ing  = (const float*)d_in[5];
    const float* b_ing  = (const float*)d_in[6];
    const float* W_tgt  = (const float*)d_in[7];
    const float* b_tgt  = (const float*)d_in[8];
    const float* Wk     = (const float*)d_in[9];
    const float* bk     = (const float*)d_in[10];
    const float* Wq     = (const float*)d_in[11];
    const float* bq     = (const float*)d_in[12];
    const float* Wv     = (const float*)d_in[13];
    const float* bv     = (const float*)d_in[14];
    const float* a_rel  = (const float*)d_in[15];
    const float* m_rel  = (const float*)d_in[16];
    const float* p_rel  = (const float*)d_in[17];
    const float* Wa     = (const float*)d_in[18];
    const float* ba     = (const float*)d_in[19];
    const float* skip   = (const float*)d_in[20];
    const float* W_out  = (const float*)d_in[21];
    const float* b_out  = (const float*)d_in[22];
    const int* src_e[4] = { (const int*)d_in[23], (const int*)d_in[25],
                            (const int*)d_in[27], (const int*)d_in[29] };
    const int* dst_e[4] = { (const int*)d_in[24], (const int*)d_in[26],
                            (const int*)d_in[28], (const int*)d_in[30] };

    const int Nh = in_sizes[0] / 400;
    const int Ni = in_sizes[1] / 300;
    const int Nt = in_sizes[2] / 200;
    const int NN = Nh + Ni + Nt;
    int E[4] = { in_sizes[23], in_sizes[25], in_sizes[27], in_sizes[29] };

    float *q, *krel, *vrel, *bfp;
    cudaGetSymbolAddress((void**)&q, g_q);
    cudaGetSymbolAddress((void**)&krel, g_krel);
    cudaGetSymbolAddress((void**)&vrel, g_vrel);
    cudaGetSymbolAddress((void**)&bfp, g_bf);

    int *deg, *rowptr, *pos, *erec, *bsum;
    cudaGetSymbolAddress((void**)&deg, g_deg);
    cudaGetSymbolAddress((void**)&rowptr, g_rowptr);
    cudaGetSymbolAddress((void**)&pos, g_pos);
    cudaGetSymbolAddress((void**)&erec, g_erec);
    cudaGetSymbolAddress((void**)&bsum, g_bsum);

    __half *xih, *xil, *xsh, *xsl, *gbh, *gbl, *hth, *htl, *wth;
    cudaGetSymbolAddress((void**)&xih, g_xih);
    cudaGetSymbolAddress((void**)&xil, g_xil);
    cudaGetSymbolAddress((void**)&xsh, g_xsh);
    cudaGetSymbolAddress((void**)&xsl, g_xsl);
    cudaGetSymbolAddress((void**)&gbh, g_gbh);
    cudaGetSymbolAddress((void**)&gbl, g_gbl);
    cudaGetSymbolAddress((void**)&hth, g_hth);
    cudaGetSymbolAddress((void**)&htl, g_htl);
    cudaGetSymbolAddress((void**)&wth, g_wth);

    cudaFuncSetAttribute(tgemm, cudaFuncAttributeMaxDynamicSharedMemorySize, TG_SMEM);

    static cudaStream_t sB = nullptr, sC = nullptr;
    static cudaEvent_t evRoot = nullptr, evC = nullptr, ev2a = nullptr,
                       ev2b = nullptr, evAH = nullptr, evG3 = nullptr;
    if (sB == nullptr) {
        cudaStreamCreateWithFlags(&sB, cudaStreamNonBlocking);
        cudaStreamCreateWithFlags(&sC, cudaStreamNonBlocking);
        cudaEventCreateWithFlags(&evRoot, cudaEventDisableTiming);
        cudaEventCreateWithFlags(&evC, cudaEventDisableTiming);
        cudaEventCreateWithFlags(&ev2a, cudaEventDisableTiming);
        cudaEventCreateWithFlags(&ev2b, cudaEventDisableTiming);
        cudaEventCreateWithFlags(&evAH, cudaEventDisableTiming);
        cudaEventCreateWithFlags(&evG3, cudaEventDisableTiming);
    }

    const int offT3[3]   = { 0, Nh, Nh + Ni };
    const int slotOff[4] = { 0, Nh, Nh + Ni, Nh + 2 * Ni };
    const int dstOff[4]  = { Nh, 0, Nh + Ni, Nh };
    const int Ntype[3]   = { Nh, Ni, Nt };

    EArr ea;
    for (int e = 0; e < 4; ++e) {
        ea.src[e] = src_e[e]; ea.dst[e] = dst_e[e];
        ea.E[e] = E[e]; ea.base[e] = dstOff[e]; ea.slot[e] = slotOff[e];
    }

    // fork
    cudaEventRecord(evRoot, 0);
    cudaStreamWaitEvent(sB, evRoot, 0);
    cudaStreamWaitEvent(sC, evRoot, 0);

    // ---- stream B: CSR build
    zero_deg<<<cdiv(NN, 256), 256, 0, sB>>>(deg, NN);
    hist_deg<<<dim3(128, 4), 256, 0, sB>>>(ea, deg);
    const int NB = cdiv(NN, 256);
    scan1<<<NB, 256, 0, sB>>>(deg, rowptr, bsum, NN);
    scan2<<<1, 512, 0, sB>>>(bsum, NB);
    scan3<<<NB, 256, 0, sB>>>(deg, rowptr, bsum, pos, NN);
    scatter_edges<<<dim3(128, 4), 256, 0, sB>>>(ea, pos, erec);

    // ---- stream C: input converts + weight transposes
    const size_t xiI = (size_t)Nh * KH;
    const size_t xiT = xiI + (size_t)Ni * KI;
    convert_pad4<<<cdiv(Nh * KH / 4, 256), 256, 0, sC>>>(x_herb, xih,       xil,       Nh, 400, KH);
    convert_pad4<<<cdiv(Ni * KI / 4, 256), 256, 0, sC>>>(x_ing,  xih + xiI, xil + xiI, Ni, 300, KI);
    convert_pad4<<<cdiv(Nt * KT / 4, 256), 256, 0, sC>>>(x_tgt,  xih + xiT, xil + xiT, Nt, 200, KT);
    {
        TJobs T{};
        int t = 0;
        T.j[t++] = { W_herb, wth + WH_OFF, 400, KH };
        T.j[t++] = { W_ing,  wth + WI_OFF, 300, KI };
        T.j[t++] = { W_tgt,  wth + WT_OFF, 200, KT };
        for (int i = 0; i < 3; ++i)
            T.j[t++] = { Wq + (size_t)i*HID*HID, wth + WQ_OFF + i*16384, 128, 128 };
        for (int i = 0; i < 3; ++i)
            T.j[t++] = { Wa + (size_t)i*HID*HID, wth + WA_OFF + i*16384, 128, 128 };
        T.j[t++] = { W_out, wth + WO_OFF, 128, 128 };
        transpose_wt<<<dim3(64, 10), 256, 0, sC>>>(T);
    }
    cudaEventRecord(evC, sC);

    // ---- main stream: fuse then dense chain
    fuse_rel_weights<<<8, 256>>>(Wk, bk, Wv, bv, a_rel, m_rel, p_rel, wth, bfp);
    cudaStreamWaitEvent(0, evC, 0);

    // GEMM1: input projections -> xs fp16 h/l only (2-term)
    {
        GJobs J{}; int nb = 0;
        auto add = [&](const __half* ah, const __half* al, int woff,
                       const float* b, __half* dh, __half* dl, int M, int K) {
            J.j[J.njobs] = { ah, al, wth + woff, b, nullptr,
                             nullptr, nullptr, dh, dl, M, K, 6, 0, nb };
            J.njobs++; nb += cdiv(M, 128);
        };
        add(xih,       xil,       WH_OFF, b_herb,
            xsh,                       xsl,                       Nh, KH);
        add(xih + xiI, xil + xiI, WI_OFF, b_ing,
            xsh + (size_t)Nh*HID,      xsl + (size_t)Nh*HID,      Ni, KI);
        add(xih + xiT, xil + xiT, WT_OFF, b_tgt,
            xsh + (size_t)(Nh+Ni)*HID, xsl + (size_t)(Nh+Ni)*HID, Nt, KT);
        tgemm<<<nb, 256, TG_SMEM>>>(J, skip);
    }

    // GEMM2a: herb-attend prerequisites (q_herb 2-term; kr1/vr1 single-term)
    {
        GJobs J{}; int nb = 0;
        auto add = [&](int xoff, int woff, const float* b, float* d, int M, int mode) {
            J.j[J.njobs] = { xsh + (size_t)xoff*HID, xsl + (size_t)xoff*HID,
                             wth + woff, b, d,
                             nullptr, nullptr, nullptr, nullptr, M, 128, mode, 0, nb };
            J.njobs++; nb += cdiv(M, 128);
        };
        add(0,  WQ_OFF,           bq,          q,                             Nh, 0);
        add(Nh, WF_OFF + 2*16384, bfp + 2*HID, krel + (size_t)slotOff[1]*HID, Ni, 8);
        add(Nh, WF_OFF + 3*16384, bfp + 3*HID, vrel + (size_t)slotOff[1]*HID, Ni, 8);
        tgemm<<<nb, 256, TG_SMEM>>>(J, skip);
    }
    cudaEventRecord(ev2a, 0);

    // GEMM2b: remaining projections (q 2-term; kr/vr single-term)
    {
        GJobs J{}; int nb = 0;
        auto add = [&](int xoff, int woff, const float* b, float* d, int M, int mode) {
            J.j[J.njobs] = { xsh + (size_t)xoff*HID, xsl + (size_t)xoff*HID,
                             wth + woff, b, d,
                             nullptr, nullptr, nullptr, nullptr, M, 128, mode, 0, nb };
            J.njobs++; nb += cdiv(M, 128);
        };
        add(Nh,      WQ_OFF + 1*16384, bq + 1*HID,  q + (size_t)Nh*HID,            Ni, 0);
        add(0,       WF_OFF + 0*16384, bfp + 0*HID, krel + (size_t)slotOff[0]*HID, Nh, 8);
        add(0,       WF_OFF + 1*16384, bfp + 1*HID, vrel + (size_t)slotOff[0]*HID, Nh, 8);
        add(Nh,      WF_OFF + 4*16384, bfp + 4*HID, krel + (size_t)slotOff[2]*HID, Ni, 8);
        add(Nh,      WF_OFF + 5*16384, bfp + 5*HID, vrel + (size_t)slotOff[2]*HID, Ni, 8);
        add(Nh + Ni, WQ_OFF + 2*16384, bq + 2*HID,  q + (size_t)(Nh+Ni)*HID,       Nt, 0);
        add(Nh + Ni, WF_OFF + 6*16384, bfp + 6*HID, krel + (size_t)slotOff[3]*HID, Nt, 8);
        add(Nh + Ni, WF_OFF + 7*16384, bfp + 7*HID, vrel + (size_t)slotOff[3]*HID, Nt, 8);
        tgemm<<<nb, 256, TG_SMEM>>>(J, skip);
    }
    cudaEventRecord(ev2b, 0);

    // ---- stream B: herb attend, then rest + GEMM3 ing/tgt
    float* outp = (float*)d_out;
    cudaStreamWaitEvent(sB, ev2a, 0);
    attend<<<cdiv(Nh * 32, 256), 256, 0, sB>>>(rowptr, erec, q, krel, vrel,
                                               gbh, gbl, 0, Nh);
    cudaEventRecord(evAH, sB);
    cudaStreamWaitEvent(sB, ev2b, 0);
    attend<<<cdiv((NN - Nh) * 32, 256), 256, 0, sB>>>(rowptr, erec, q, krel, vrel,
                                                      gbh, gbl, Nh, NN);
    {   // GEMM3 ing + tgt -> d_out directly (2-term)
        GJobs J{}; int nb = 0;
        for (int i = 1; i < 3; ++i) {
            float* d = (i == 1) ? outp + (size_t)Nh*HID : outp + (size_t)(Nh+Ni)*HID;
            J.j[J.njobs] = { gbh + (size_t)offT3[i]*HID, gbl + (size_t)offT3[i]*HID,
                             wth + WA_OFF + i*16384, ba + i*HID, d,
                             xsh + (size_t)offT3[i]*HID, xsl + (size_t)offT3[i]*HID,
                             nullptr, nullptr, Ntype[i], 128, 1, i, nb };
            J.njobs++; nb += cdiv(Ntype[i], 128);
        }
        tgemm<<<nb, 256, TG_SMEM, sB>>>(J, skip);
    }
    cudaEventRecord(evG3, sB);

    // ---- main: herb output chain
    cudaStreamWaitEvent(0, evAH, 0);
    {   // GEMM3 herb -> hth/htl (fp16 h/l only, 2-term)
        GJobs J{};
        J.j[0] = { gbh, gbl, wth + WA_OFF, ba, nullptr,
                   xsh, xsl, hth, htl, Nh, 128, 1 | 2 | 4, 0, 0 };
        J.njobs = 1;
        tgemm<<<cdiv(Nh, 128), 256, TG_SMEM>>>(J, skip);
    }
    cudaStreamWaitEvent(0, evG3, 0);
    {   // GEMM4: final herb linear (2-term)
        GJobs J{};
        J.j[0] = { hth, htl, wth + WO_OFF, b_out, outp,
                   nullptr, nullptr, nullptr, nullptr, Nh, 128, 0, 0, 0 };
        J.njobs = 1;
        tgemm<<<cdiv(Nh, 128), 256, TG_SMEM>>>(J, skip);
    }
}

// round 16
// speedup vs baseline: 1.1127x; 1.0294x over previous
#include <cuda_runtime.h>
#include <cuda_fp16.h>
#include <cstdint>
#include <math.h>

// ---------------------------------------------------------------------------
// Problem constants
// ---------------------------------------------------------------------------
#define HID 128
#define NHEAD 8
#define HDIM 16

#define NH_MAX 8000
#define NI_MAX 40000
#define NT_MAX 20000
#define NN_MAX (NH_MAX + NI_MAX + NT_MAX)           // 68000
#define NREL_MAX (NH_MAX + 2*NI_MAX + NT_MAX)       // 108000
#define MAXE 250000

// padded K for inputs (multiple of 8 for 16B cp.async alignment)
#define KH 400
#define KI 304
#define KT 200
#define XI_TOTAL ((size_t)NH_MAX*KH + (size_t)NI_MAX*KI + (size_t)NT_MAX*KT)

// fp16 weight pool offsets (transposed [128][Kp])
#define WH_OFF 0
#define WI_OFF 51200
#define WT_OFF 90112
#define WQ_OFF 115712
#define WF_OFF 164864
#define WA_OFF 295936
#define WO_OFF 345088
#define WPOOL  361472

// ---------------------------------------------------------------------------
// Device scratch
// ---------------------------------------------------------------------------
__device__ float g_q    [(size_t)NN_MAX   * HID];
__device__ float g_krel [(size_t)NREL_MAX * HID];
__device__ float g_vrel [(size_t)NREL_MAX * HID];
__device__ float g_bf   [8 * HID];

__device__ int g_deg   [NN_MAX];
__device__ int g_rowptr[NN_MAX + 1];
__device__ int g_pos   [NN_MAX];
__device__ int g_erec  [4 * MAXE];
__device__ int g_bsum  [512];

__device__ __half g_xih[XI_TOTAL];
__device__ __half g_xil[XI_TOTAL];
__device__ __half g_xsh[(size_t)NN_MAX * HID];
__device__ __half g_xsl[(size_t)NN_MAX * HID];
__device__ __half g_gbh[(size_t)NN_MAX * HID];
__device__ __half g_gbl[(size_t)NN_MAX * HID];
__device__ __half g_hth[(size_t)NH_MAX * HID];
__device__ __half g_htl[(size_t)NH_MAX * HID];
__device__ __half g_wth[WPOOL];

// ---------------------------------------------------------------------------
// Fuse Wk/Wv with per-edge-type relation matrices; p_rel/sqrtD folded into
// k-kind. Writes TRANSPOSED fp16 directly into the weight pool.
// ---------------------------------------------------------------------------
__global__ void fuse_rel_weights(const float* __restrict__ Wk, const float* __restrict__ bk,
                                 const float* __restrict__ Wv, const float* __restrict__ bv,
                                 const float* __restrict__ a_rel, const float* __restrict__ m_rel,
                                 const float* __restrict__ prel,
                                 __half* __restrict__ wth, float* __restrict__ bf)
{
    int slot = blockIdx.x;
    int e = slot >> 1, kind = slot & 1;
    int s = (e == 0) ? 0 : ((e == 3) ? 2 : 1);
    const float* Wb = (kind ? Wv : Wk) + (size_t)s * HID * HID;
    const float* bb = (kind ? bv : bk) + (size_t)s * HID;
    const float* rel = (kind ? m_rel : a_rel) + (size_t)e * NHEAD * HDIM * HDIM;

    for (int idx = threadIdx.x; idx < HID * HID; idx += blockDim.x) {
        int i = idx >> 7, j = idx & 127;
        int h = j >> 4, j16 = j & 15;
        float acc = 0.0f;
        #pragma unroll
        for (int d = 0; d < HDIM; ++d)
            acc += Wb[i * HID + h * HDIM + d] * rel[(h * HDIM + d) * HDIM + j16];
        if (kind == 0) acc *= prel[e * NHEAD + h] * 0.25f;
        wth[(size_t)WF_OFF + (size_t)slot * 16384 + j * 128 + i] = __float2half_rn(acc);
    }
    for (int j = threadIdx.x; j < HID; j += blockDim.x) {
        int h = j >> 4, j16 = j & 15;
        float acc = 0.0f;
        #pragma unroll
        for (int d = 0; d < HDIM; ++d)
            acc += bb[h * HDIM + d] * rel[(h * HDIM + d) * HDIM + j16];
        if (kind == 0) acc *= prel[e * NHEAD + h] * 0.25f;
        bf[slot * HID + j] = acc;
    }
}

// ---------------------------------------------------------------------------
// fp32 -> fp16 hi/lo, vectorized (4 elems/thread), with K padding
// ---------------------------------------------------------------------------
__global__ void convert_pad4(const float* __restrict__ src,
                             __half* __restrict__ dh, __half* __restrict__ dl,
                             int M, int K, int Kp)
{
    int idx4 = blockIdx.x * blockDim.x + threadIdx.x;
    int kq = Kp >> 2;
    if (idx4 >= M * kq) return;
    int r = idx4 / kq, k4 = (idx4 - r * kq) << 2;
    float4 v = make_float4(0.f, 0.f, 0.f, 0.f);
    if (k4 < K)
        v = *reinterpret_cast<const float4*>(src + (size_t)r * K + k4);
    __half2 h01, h23, l01, l23;
    h01.x = __float2half_rn(v.x); h01.y = __float2half_rn(v.y);
    h23.x = __float2half_rn(v.z); h23.y = __float2half_rn(v.w);
    l01.x = __float2half_rn(v.x - __half2float(h01.x));
    l01.y = __float2half_rn(v.y - __half2float(h01.y));
    l23.x = __float2half_rn(v.z - __half2float(h23.x));
    l23.y = __float2half_rn(v.w - __half2float(h23.y));
    *reinterpret_cast<__half2*>(dh + (size_t)idx4 * 4)     = h01;
    *reinterpret_cast<__half2*>(dh + (size_t)idx4 * 4 + 2) = h23;
    *reinterpret_cast<__half2*>(dl + (size_t)idx4 * 4)     = l01;
    *reinterpret_cast<__half2*>(dl + (size_t)idx4 * 4 + 2) = l23;
}

// ---------------------------------------------------------------------------
// Weight transpose + fp16: W [K][128] fp32 -> Wt [128][Kp] fp16
// ---------------------------------------------------------------------------
struct TJob { const float* W; __half* th; int K; int Kp; };
struct TJobs { TJob j[10]; };

__global__ void transpose_wt(TJobs jobs)
{
    TJob jb = jobs.j[blockIdx.y];
    int total = 128 * jb.Kp;
    for (int idx = blockIdx.x * blockDim.x + threadIdx.x; idx < total;
         idx += gridDim.x * blockDim.x) {
        int n = idx / jb.Kp, k = idx - n * jb.Kp;
        float v = (k < jb.K) ? jb.W[(size_t)k * 128 + n] : 0.0f;
        jb.th[idx] = __float2half_rn(v);
    }
}

// ---------------------------------------------------------------------------
// CSR build
// ---------------------------------------------------------------------------
struct EArr { const int* src[4]; const int* dst[4]; int E[4]; int base[4]; int slot[4]; };

__global__ void zero_deg(int* __restrict__ deg, int NN)
{
    int i = blockIdx.x * blockDim.x + threadIdx.x;
    if (i < NN) deg[i] = 0;
}

__global__ void hist_deg(EArr ea, int* __restrict__ deg)
{
    int e = blockIdx.y;
    const int* dst = ea.dst[e];
    int E = ea.E[e], base = ea.base[e];
    for (int i = blockIdx.x * blockDim.x + threadIdx.x; i < E;
         i += gridDim.x * blockDim.x)
        atomicAdd(&deg[base + dst[i]], 1);
}

__global__ void scan1(const int* __restrict__ deg, int* __restrict__ rowptr,
                      int* __restrict__ bsum, int NN)
{
    __shared__ int ws[8];
    int i = blockIdx.x * 256 + threadIdx.x;
    int lane = threadIdx.x & 31, w = threadIdx.x >> 5;
    int x = (i < NN) ? deg[i] : 0;
    #pragma unroll
    for (int o = 1; o < 32; o <<= 1) {
        int y = __shfl_up_sync(0xffffffffu, x, o);
        if (lane >= o) x += y;
    }
    if (lane == 31) ws[w] = x;
    __syncthreads();
    if (threadIdx.x < 8) {
        int y = ws[threadIdx.x];
        #pragma unroll
        for (int o = 1; o < 8; o <<= 1) {
            int z = __shfl_up_sync(0xffu, y, o);
            if ((int)threadIdx.x >= o) y += z;
        }
        ws[threadIdx.x] = y;
    }
    __syncthreads();
    if (w > 0) x += ws[w - 1];
    if (i < NN) rowptr[i + 1] = x;
    if (threadIdx.x == 255) bsum[blockIdx.x] = x;
}

__global__ void scan2(int* __restrict__ bsum, int NB)
{
    __shared__ int s[512];
    int t = threadIdx.x;
    int orig = (t < NB) ? bsum[t] : 0;
    s[t] = orig;
    __syncthreads();
    for (int o = 1; o < 512; o <<= 1) {
        int v = (t >= o) ? s[t - o] : 0;
        __syncthreads();
        s[t] += v;
        __syncthreads();
    }
    if (t < NB) bsum[t] = s[t] - orig;
}

__global__ void scan3(const int* __restrict__ deg, int* __restrict__ rowptr,
                      const int* __restrict__ bsum, int* __restrict__ pos, int NN)
{
    int i = blockIdx.x * 256 + threadIdx.x;
    if (i >= NN) return;
    int val = rowptr[i + 1] + bsum[blockIdx.x];
    rowptr[i + 1] = val;
    pos[i] = val - deg[i];
    if (i == 0) rowptr[0] = 0;
}

__global__ void scatter_edges(EArr ea, int* __restrict__ pos, int* __restrict__ erec)
{
    int e = blockIdx.y;
    const int* src = ea.src[e];
    const int* dst = ea.dst[e];
    int E = ea.E[e], base = ea.base[e], slot = ea.slot[e];
    for (int i = blockIdx.x * blockDim.x + threadIdx.x; i < E;
         i += gridDim.x * blockDim.x) {
        int p = atomicAdd(&pos[base + dst[i]], 1);
        erec[p] = slot + src[i];
    }
}

// ---------------------------------------------------------------------------
// Fused attention, node range [n0, n1). One warp per dst node.
// Softmax WITHOUT running-max subtraction: logits are sigma~1 by construction
// (max over all edges ~5.5 sigma; expf overflows at 88 ~ 25+ sigma), so
// den += exp(p); acc += exp(p)*v is safe and removes the serial rescale
// chain (full ILP across edges). 2-deep gather prefetch.
// Writes gelu(agg/den) as fp16 h/l.
// ---------------------------------------------------------------------------
__global__ __launch_bounds__(256)
void attend(const int* __restrict__ rowptr, const int* __restrict__ erec,
            const float* __restrict__ q, const float* __restrict__ krel,
            const float* __restrict__ vrel,
            __half* __restrict__ oh, __half* __restrict__ ol,
            int n0, int n1)
{
    const int n = n0 + ((blockIdx.x * blockDim.x + threadIdx.x) >> 5);
    const int lane = threadIdx.x & 31;
    if (n >= n1) return;

    const int lo = rowptr[n], hi = rowptr[n + 1];
    const float4 qv = *reinterpret_cast<const float4*>(q + (size_t)n * HID + lane * 4);

    float den = 0.0f;
    float4 acc = make_float4(0.f, 0.f, 0.f, 0.f);

    float4 k0, v0, k1, v1;
    if (lo < hi) {
        int ss = __ldg(erec + lo);
        k0 = *reinterpret_cast<const float4*>(krel + (size_t)ss * HID + lane * 4);
        v0 = *reinterpret_cast<const float4*>(vrel + (size_t)ss * HID + lane * 4);
    }
    if (lo + 1 < hi) {
        int ss = __ldg(erec + lo + 1);
        k1 = *reinterpret_cast<const float4*>(krel + (size_t)ss * HID + lane * 4);
        v1 = *reinterpret_cast<const float4*>(vrel + (size_t)ss * HID + lane * 4);
    }
    for (int i = lo; i < hi; ++i) {
        float4 kv = k0, vv = v0;
        k0 = k1; v0 = v1;
        if (i + 2 < hi) {
            int ss = __ldg(erec + i + 2);
            k1 = *reinterpret_cast<const float4*>(krel + (size_t)ss * HID + lane * 4);
            v1 = *reinterpret_cast<const float4*>(vrel + (size_t)ss * HID + lane * 4);
        }
        float p = qv.x * kv.x + qv.y * kv.y + qv.z * kv.z + qv.w * kv.w;
        p += __shfl_xor_sync(0xffffffffu, p, 1);
        p += __shfl_xor_sync(0xffffffffu, p, 2);   // full logit (p_rel folded in)
        float ex = __expf(p);
        den += ex;
        acc.x = fmaf(ex, vv.x, acc.x);
        acc.y = fmaf(ex, vv.y, acc.y);
        acc.z = fmaf(ex, vv.z, acc.z);
        acc.w = fmaf(ex, vv.w, acc.w);
    }

    const float inv = 1.0f / (den + 1e-16f);
    float o[4] = { acc.x * inv, acc.y * inv, acc.z * inv, acc.w * inv };
    #pragma unroll
    for (int j = 0; j < 4; ++j)
        o[j] = 0.5f * o[j] * (1.0f + erff(o[j] * 0.70710678118654752f));
    __half2 h01, h23, l01, l23;
    h01.x = __float2half_rn(o[0]); h01.y = __float2half_rn(o[1]);
    h23.x = __float2half_rn(o[2]); h23.y = __float2half_rn(o[3]);
    l01.x = __float2half_rn(o[0] - __half2float(h01.x));
    l01.y = __float2half_rn(o[1] - __half2float(h01.y));
    l23.x = __float2half_rn(o[2] - __half2float(h23.x));
    l23.y = __float2half_rn(o[3] - __half2float(h23.y));
    size_t ob = (size_t)n * HID + lane * 4;
    *reinterpret_cast<__half2*>(oh + ob)     = h01;
    *reinterpret_cast<__half2*>(oh + ob + 2) = h23;
    *reinterpret_cast<__half2*>(ol + ob)     = l01;
    *reinterpret_cast<__half2*>(ol + ob + 2) = l23;
}

// ---------------------------------------------------------------------------
// fp16 split-precision tensor-core GEMM (mma.sync; compute_103-safe).
// 2-term: D = (Ah + Al) @ B ; 1-term (mode bit3): D = Ah @ B
// mode bit0: skip-gate epilogue (x from fp16 h/l pair)
// mode bit1: write fp16 h/l outputs
// mode bit2: skip fp32 output write
// mode bit3: single-term A (for softmax-bound outputs; halves MMA count)
// ---------------------------------------------------------------------------
#define KC 32
#define PADK 40
#define CHB (128 * PADK)
#define TG_SMEM (6 * CHB * 2)      // 2 stages x 3 arrays (ah, al, b)

struct GJob { const __half *Ah, *Al, *B;
              const float *bias; float *dst;
              const __half *gxh, *gxl;
              __half *dsth, *dstl;
              int M, K, mode, skipidx, blk0; };
struct GJobs { GJob j[11]; int njobs; };

__device__ __forceinline__ uint32_t smem_u32(const void* p) {
    uint32_t a;
    asm("{ .reg .u64 t; cvta.to.shared.u64 t, %1; cvt.u32.u64 %0, t; }" : "=r"(a) : "l"(p));
    return a;
}

#define CPASYNC(dst, src, sz)                                                 \
    asm volatile("cp.async.ca.shared.global [%0], [%1], 16, %2;"              \
        :: "r"(dst), "l"(src), "r"(sz))

#define LDSM4(r0, r1, r2, r3, addr)                                           \
    asm volatile("ldmatrix.sync.aligned.m8n8.x4.shared.b16 {%0,%1,%2,%3}, [%4];" \
        : "=r"(r0), "=r"(r1), "=r"(r2), "=r"(r3) : "r"(addr))

#define MMA_FP16(d, a, b)                                                     \
    asm volatile("mma.sync.aligned.m16n8k16.row.col.f32.f16.f16.f32 "         \
        "{%0,%1,%2,%3}, {%4,%5,%6,%7}, {%8,%9}, {%0,%1,%2,%3};"               \
        : "+f"((d)[0]), "+f"((d)[1]), "+f"((d)[2]), "+f"((d)[3])              \
        : "r"((a)[0]), "r"((a)[1]), "r"((a)[2]), "r"((a)[3]),                 \
          "r"((b)[0]), "r"((b)[1]))

__global__ __launch_bounds__(256, 2)
void tgemm(GJobs jobs, const float* __restrict__ skipv)
{
    extern __shared__ __half sm[];
    const uint32_t base = smem_u32(sm);
    const int tid = threadIdx.x;
    const int wid = tid >> 5, lane = tid & 31;
    const int wm = wid & 1, wn = wid >> 1;

    int ji = 0;
    #pragma unroll 1
    for (int t = 1; t < jobs.njobs; ++t)
        if ((int)blockIdx.x >= jobs.j[t].blk0) ji = t;
    const GJob jb = jobs.j[ji];
    const int m0 = ((int)blockIdx.x - jb.blk0) * 128;
    const int M = jb.M, K = jb.K;
    const bool twoTerm = !(jb.mode & 8);

    float acc[4][4][4];
    #pragma unroll
    for (int mi = 0; mi < 4; ++mi)
        #pragma unroll
        for (int ni = 0; ni < 4; ++ni)
            #pragma unroll
            for (int r = 0; r < 4; ++r) acc[mi][ni][r] = 0.0f;

    const int a_row = ((lane >> 3) & 1) * 8 + (lane & 7);
    const int a_col = (lane >> 4) * 8;
    const int b_row = (lane >> 4) * 8 + (lane & 7);
    const int b_col = ((lane >> 3) & 1) * 8;

    const int lr = tid >> 2;
    const int lk = (tid & 3) * 8;

    const int kch = (K + KC - 1) / KC;

    auto load_chunk = [&](int c, int b) {
        const int k0 = c * KC;
        const uint32_t bb = base + (uint32_t)b * (3 * CHB * 2);
        #pragma unroll
        for (int i = 0; i < 2; ++i) {
            int r = lr + i * 64;
            int gk = k0 + lk;
            uint32_t off = (uint32_t)(r * PADK + lk) * 2;
            int okA = (m0 + r < M) && (gk < K) ? 16 : 0;
            size_t aoff = okA ? ((size_t)(m0 + r) * K + gk) : 0;
            CPASYNC(bb + off, jb.Ah + aoff, okA);
            if (twoTerm)
                CPASYNC(bb + off + CHB * 2, jb.Al + aoff, okA);
            int okB = (gk < K) ? 16 : 0;
            size_t boff = okB ? ((size_t)r * K + gk) : 0;
            CPASYNC(bb + off + 2 * CHB * 2, jb.B + boff, okB);
        }
        asm volatile("cp.async.commit_group;" ::: "memory");
    };

    load_chunk(0, 0);

    for (int c = 0; c < kch; ++c) {
        const int b = c & 1;
        asm volatile("cp.async.wait_group 0;" ::: "memory");
        // one barrier: publishes buf b AND orders prior compute on b^1
        // before the load below overwrites it
        __syncthreads();
        if (c + 1 < kch) load_chunk(c + 1, b ^ 1);

        const uint32_t bb = base + (uint32_t)b * (3 * CHB * 2);
        #pragma unroll
        for (int kk = 0; kk < 2; ++kk) {
            uint32_t ah[4][4], al[4][4], bf2[4][2];
            #pragma unroll
            for (int mi = 0; mi < 4; ++mi) {
                int row = wm * 64 + mi * 16 + a_row;
                int col = kk * 16 + a_col;
                uint32_t off = bb + (uint32_t)(row * PADK + col) * 2;
                LDSM4(ah[mi][0], ah[mi][1], ah[mi][2], ah[mi][3], off);
                if (twoTerm)
                    LDSM4(al[mi][0], al[mi][1], al[mi][2], al[mi][3], off + CHB * 2);
            }
            #pragma unroll
            for (int p = 0; p < 2; ++p) {
                int row = wn * 32 + p * 16 + b_row;
                int col = kk * 16 + b_col;
                uint32_t off = bb + 2 * CHB * 2 + (uint32_t)(row * PADK + col) * 2;
                LDSM4(bf2[2*p][0], bf2[2*p][1], bf2[2*p+1][0], bf2[2*p+1][1], off);
            }
            #pragma unroll
            for (int mi = 0; mi < 4; ++mi)
                #pragma unroll
                for (int ni = 0; ni < 4; ++ni) {
                    MMA_FP16(acc[mi][ni], ah[mi], bf2[ni]);
                    if (twoTerm)
                        MMA_FP16(acc[mi][ni], al[mi], bf2[ni]);
                }
        }
    }

    float g = 0.f, hg = 0.f;
    if (jb.mode & 1) {
        g = 1.f / (1.f + expf(-skipv[jb.skipidx]));
        hg = 1.f - g;
    }
    const int r4 = lane >> 2, c2 = (lane & 3) * 2;
    #pragma unroll
    for (int mi = 0; mi < 4; ++mi) {
        #pragma unroll
        for (int ni = 0; ni < 4; ++ni) {
            int gcol = wn * 32 + ni * 8 + c2;
            float2 bb2 = *reinterpret_cast<const float2*>(jb.bias + gcol);
            #pragma unroll
            for (int half = 0; half < 2; ++half) {
                int gr = m0 + wm * 64 + mi * 16 + r4 + half * 8;
                if (gr >= M) continue;
                float2 o;
                o.x = acc[mi][ni][half * 2 + 0] + bb2.x;
                o.y = acc[mi][ni][half * 2 + 1] + bb2.y;
                if (jb.mode & 1) {
                    __half2 xh2 = *reinterpret_cast<const __half2*>(
                        jb.gxh + (size_t)gr * HID + gcol);
                    __half2 xl2 = *reinterpret_cast<const __half2*>(
                        jb.gxl + (size_t)gr * HID + gcol);
                    float xx = __half2float(xh2.x) + __half2float(xl2.x);
                    float xy = __half2float(xh2.y) + __half2float(xl2.y);
                    o.x = fmaxf(0.f, g * o.x + hg * xx);
                    o.y = fmaxf(0.f, g * o.y + hg * xy);
                }
                if (!(jb.mode & 4))
                    *reinterpret_cast<float2*>(jb.dst + (size_t)gr * HID + gcol) = o;
                if (jb.mode & 2) {
                    __half2 h2, l2;
                    h2.x = __float2half_rn(o.x);
                    h2.y = __float2half_rn(o.y);
                    l2.x = __float2half_rn(o.x - __half2float(h2.x));
                    l2.y = __float2half_rn(o.y - __half2float(h2.y));
                    *reinterpret_cast<__half2*>(jb.dsth + (size_t)gr * HID + gcol) = h2;
                    *reinterpret_cast<__half2*>(jb.dstl + (size_t)gr * HID + gcol) = l2;
                }
            }
        }
    }
}

// ---------------------------------------------------------------------------
static inline int cdiv(int a, int b) { return (a + b - 1) / b; }

extern "C" void kernel_launch(void* const* d_in, const int* in_sizes, int n_in,
                              void* d_out, int out_size)
{
    const float* x_herb = (const float*)d_in[0];
    const float* x_ing  = (const float*)d_in[1];
    const float* x_tgt  = (const float*)d_in[2];
    const float* W_herb = (const float*)d_in[3];
    const float* b_herb = (const float*)d_in[4];
    const float* W_ing  = (const float*)d_in[5];
    const float* b_ing  = (const float*)d_in[6];
    const float* W_tgt  = (const float*)d_in[7];
    const float* b_tgt  = (const float*)d_in[8];
    const float* Wk     = (const float*)d_in[9];
    const float* bk     = (const float*)d_in[10];
    const float* Wq     = (const float*)d_in[11];
    const float* bq     = (const float*)d_in[12];
    const float* Wv     = (const float*)d_in[13];
    const float* bv     = (const float*)d_in[14];
    const float* a_rel  = (const float*)d_in[15];
    const float* m_rel  = (const float*)d_in[16];
    const float* p_rel  = (const float*)d_in[17];
    const float* Wa     = (const float*)d_in[18];
    const float* ba     = (const float*)d_in[19];
    const float* skip   = (const float*)d_in[20];
    const float* W_out  = (const float*)d_in[21];
    const float* b_out  = (const float*)d_in[22];
    const int* src_e[4] = { (const int*)d_in[23], (const int*)d_in[25],
                            (const int*)d_in[27], (const int*)d_in[29] };
    const int* dst_e[4] = { (const int*)d_in[24], (const int*)d_in[26],
                            (const int*)d_in[28], (const int*)d_in[30] };

    const int Nh = in_sizes[0] / 400;
    const int Ni = in_sizes[1] / 300;
    const int Nt = in_sizes[2] / 200;
    const int NN = Nh + Ni + Nt;
    int E[4] = { in_sizes[23], in_sizes[25], in_sizes[27], in_sizes[29] };

    float *q, *krel, *vrel, *bfp;
    cudaGetSymbolAddress((void**)&q, g_q);
    cudaGetSymbolAddress((void**)&krel, g_krel);
    cudaGetSymbolAddress((void**)&vrel, g_vrel);
    cudaGetSymbolAddress((void**)&bfp, g_bf);

    int *deg, *rowptr, *pos, *erec, *bsum;
    cudaGetSymbolAddress((void**)&deg, g_deg);
    cudaGetSymbolAddress((void**)&rowptr, g_rowptr);
    cudaGetSymbolAddress((void**)&pos, g_pos);
    cudaGetSymbolAddress((void**)&erec, g_erec);
    cudaGetSymbolAddress((void**)&bsum, g_bsum);

    __half *xih, *xil, *xsh, *xsl, *gbh, *gbl, *hth, *htl, *wth;
    cudaGetSymbolAddress((void**)&xih, g_xih);
    cudaGetSymbolAddress((void**)&xil, g_xil);
    cudaGetSymbolAddress((void**)&xsh, g_xsh);
    cudaGetSymbolAddress((void**)&xsl, g_xsl);
    cudaGetSymbolAddress((void**)&gbh, g_gbh);
    cudaGetSymbolAddress((void**)&gbl, g_gbl);
    cudaGetSymbolAddress((void**)&hth, g_hth);
    cudaGetSymbolAddress((void**)&htl, g_htl);
    cudaGetSymbolAddress((void**)&wth, g_wth);

    cudaFuncSetAttribute(tgemm, cudaFuncAttributeMaxDynamicSharedMemorySize, TG_SMEM);

    static cudaStream_t sB = nullptr, sC = nullptr;
    static cudaEvent_t evRoot = nullptr, evC = nullptr, ev2a = nullptr,
                       ev2b = nullptr, evAH = nullptr, evG3 = nullptr;
    if (sB == nullptr) {
        cudaStreamCreateWithFlags(&sB, cudaStreamNonBlocking);
        cudaStreamCreateWithFlags(&sC, cudaStreamNonBlocking);
        cudaEventCreateWithFlags(&evRoot, cudaEventDisableTiming);
        cudaEventCreateWithFlags(&evC, cudaEventDisableTiming);
        cudaEventCreateWithFlags(&ev2a, cudaEventDisableTiming);
        cudaEventCreateWithFlags(&ev2b, cudaEventDisableTiming);
        cudaEventCreateWithFlags(&evAH, cudaEventDisableTiming);
        cudaEventCreateWithFlags(&evG3, cudaEventDisableTiming);
    }

    const int offT3[3]   = { 0, Nh, Nh + Ni };
    const int slotOff[4] = { 0, Nh, Nh + Ni, Nh + 2 * Ni };
    const int dstOff[4]  = { Nh, 0, Nh + Ni, Nh };
    const int Ntype[3]   = { Nh, Ni, Nt };

    EArr ea;
    for (int e = 0; e < 4; ++e) {
        ea.src[e] = src_e[e]; ea.dst[e] = dst_e[e];
        ea.E[e] = E[e]; ea.base[e] = dstOff[e]; ea.slot[e] = slotOff[e];
    }

    // fork
    cudaEventRecord(evRoot, 0);
    cudaStreamWaitEvent(sB, evRoot, 0);
    cudaStreamWaitEvent(sC, evRoot, 0);

    // ---- stream B: CSR build
    zero_deg<<<cdiv(NN, 256), 256, 0, sB>>>(deg, NN);
    hist_deg<<<dim3(128, 4), 256, 0, sB>>>(ea, deg);
    const int NB = cdiv(NN, 256);
    scan1<<<NB, 256, 0, sB>>>(deg, rowptr, bsum, NN);
    scan2<<<1, 512, 0, sB>>>(bsum, NB);
    scan3<<<NB, 256, 0, sB>>>(deg, rowptr, bsum, pos, NN);
    scatter_edges<<<dim3(128, 4), 256, 0, sB>>>(ea, pos, erec);

    // ---- stream C: input converts + weight transposes
    const size_t xiI = (size_t)Nh * KH;
    const size_t xiT = xiI + (size_t)Ni * KI;
    convert_pad4<<<cdiv(Nh * KH / 4, 256), 256, 0, sC>>>(x_herb, xih,       xil,       Nh, 400, KH);
    convert_pad4<<<cdiv(Ni * KI / 4, 256), 256, 0, sC>>>(x_ing,  xih + xiI, xil + xiI, Ni, 300, KI);
    convert_pad4<<<cdiv(Nt * KT / 4, 256), 256, 0, sC>>>(x_tgt,  xih + xiT, xil + xiT, Nt, 200, KT);
    {
        TJobs T{};
        int t = 0;
        T.j[t++] = { W_herb, wth + WH_OFF, 400, KH };
        T.j[t++] = { W_ing,  wth + WI_OFF, 300, KI };
        T.j[t++] = { W_tgt,  wth + WT_OFF, 200, KT };
        for (int i = 0; i < 3; ++i)
            T.j[t++] = { Wq + (size_t)i*HID*HID, wth + WQ_OFF + i*16384, 128, 128 };
        for (int i = 0; i < 3; ++i)
            T.j[t++] = { Wa + (size_t)i*HID*HID, wth + WA_OFF + i*16384, 128, 128 };
        T.j[t++] = { W_out, wth + WO_OFF, 128, 128 };
        transpose_wt<<<dim3(64, 10), 256, 0, sC>>>(T);
    }
    cudaEventRecord(evC, sC);

    // ---- main stream: fuse then dense chain
    fuse_rel_weights<<<8, 256>>>(Wk, bk, Wv, bv, a_rel, m_rel, p_rel, wth, bfp);
    cudaStreamWaitEvent(0, evC, 0);

    // GEMM1: input projections -> xs fp16 h/l only (2-term)
    {
        GJobs J{}; int nb = 0;
        auto add = [&](const __half* ah, const __half* al, int woff,
                       const float* b, __half* dh, __half* dl, int M, int K) {
            J.j[J.njobs] = { ah, al, wth + woff, b, nullptr,
                             nullptr, nullptr, dh, dl, M, K, 6, 0, nb };
            J.njobs++; nb += cdiv(M, 128);
        };
        add(xih,       xil,       WH_OFF, b_herb,
            xsh,                       xsl,                       Nh, KH);
        add(xih + xiI, xil + xiI, WI_OFF, b_ing,
            xsh + (size_t)Nh*HID,      xsl + (size_t)Nh*HID,      Ni, KI);
        add(xih + xiT, xil + xiT, WT_OFF, b_tgt,
            xsh + (size_t)(Nh+Ni)*HID, xsl + (size_t)(Nh+Ni)*HID, Nt, KT);
        tgemm<<<nb, 256, TG_SMEM>>>(J, skip);
    }

    // GEMM2a: herb-attend prerequisites (q_herb 2-term; kr1/vr1 single-term)
    {
        GJobs J{}; int nb = 0;
        auto add = [&](int xoff, int woff, const float* b, float* d, int M, int mode) {
            J.j[J.njobs] = { xsh + (size_t)xoff*HID, xsl + (size_t)xoff*HID,
                             wth + woff, b, d,
                             nullptr, nullptr, nullptr, nullptr, M, 128, mode, 0, nb };
            J.njobs++; nb += cdiv(M, 128);
        };
        add(0,  WQ_OFF,           bq,          q,                             Nh, 0);
        add(Nh, WF_OFF + 2*16384, bfp + 2*HID, krel + (size_t)slotOff[1]*HID, Ni, 8);
        add(Nh, WF_OFF + 3*16384, bfp + 3*HID, vrel + (size_t)slotOff[1]*HID, Ni, 8);
        tgemm<<<nb, 256, TG_SMEM>>>(J, skip);
    }
    cudaEventRecord(ev2a, 0);

    // GEMM2b: remaining projections (q 2-term; kr/vr single-term)
    {
        GJobs J{}; int nb = 0;
        auto add = [&](int xoff, int woff, const float* b, float* d, int M, int mode) {
            J.j[J.njobs] = { xsh + (size_t)xoff*HID, xsl + (size_t)xoff*HID,
                             wth + woff, b, d,
                             nullptr, nullptr, nullptr, nullptr, M, 128, mode, 0, nb };
            J.njobs++; nb += cdiv(M, 128);
        };
        add(Nh,      WQ_OFF + 1*16384, bq + 1*HID,  q + (size_t)Nh*HID,            Ni, 0);
        add(0,       WF_OFF + 0*16384, bfp + 0*HID, krel + (size_t)slotOff[0]*HID, Nh, 8);
        add(0,       WF_OFF + 1*16384, bfp + 1*HID, vrel + (size_t)slotOff[0]*HID, Nh, 8);
        add(Nh,      WF_OFF + 4*16384, bfp + 4*HID, krel + (size_t)slotOff[2]*HID, Ni, 8);
        add(Nh,      WF_OFF + 5*16384, bfp + 5*HID, vrel + (size_t)slotOff[2]*HID, Ni, 8);
        add(Nh + Ni, WQ_OFF + 2*16384, bq + 2*HID,  q + (size_t)(Nh+Ni)*HID,       Nt, 0);
        add(Nh + Ni, WF_OFF + 6*16384, bfp + 6*HID, krel + (size_t)slotOff[3]*HID, Nt, 8);
        add(Nh + Ni, WF_OFF + 7*16384, bfp + 7*HID, vrel + (size_t)slotOff[3]*HID, Nt, 8);
        tgemm<<<nb, 256, TG_SMEM>>>(J, skip);
    }
    cudaEventRecord(ev2b, 0);

    // ---- stream B: herb attend, then rest + GEMM3 ing/tgt
    float* outp = (float*)d_out;
    cudaStreamWaitEvent(sB, ev2a, 0);
    attend<<<cdiv(Nh * 32, 256), 256, 0, sB>>>(rowptr, erec, q, krel, vrel,
                                               gbh, gbl, 0, Nh);
    cudaEventRecord(evAH, sB);
    cudaStreamWaitEvent(sB, ev2b, 0);
    attend<<<cdiv((NN - Nh) * 32, 256), 256, 0, sB>>>(rowptr, erec, q, krel, vrel,
                                                      gbh, gbl, Nh, NN);
    {   // GEMM3 ing + tgt -> d_out directly (2-term)
        GJobs J{}; int nb = 0;
        for (int i = 1; i < 3; ++i) {
            float* d = (i == 1) ? outp + (size_t)Nh*HID : outp + (size_t)(Nh+Ni)*HID;
            J.j[J.njobs] = { gbh + (size_t)offT3[i]*HID, gbl + (size_t)offT3[i]*HID,
                             wth + WA_OFF + i*16384, ba + i*HID, d,
                             xsh + (size_t)offT3[i]*HID, xsl + (size_t)offT3[i]*HID,
                             nullptr, nullptr, Ntype[i], 128, 1, i, nb };
            J.njobs++; nb += cdiv(Ntype[i], 128);
        }
        tgemm<<<nb, 256, TG_SMEM, sB>>>(J, skip);
    }
    cudaEventRecord(evG3, sB);

    // ---- main: herb output chain
    cudaStreamWaitEvent(0, evAH, 0);
    {   // GEMM3 herb -> hth/htl (fp16 h/l only, 2-term)
        GJobs J{};
        J.j[0] = { gbh, gbl, wth + WA_OFF, ba, nullptr,
                   xsh, xsl, hth, htl, Nh, 128, 1 | 2 | 4, 0, 0 };
        J.njobs = 1;
        tgemm<<<cdiv(Nh, 128), 256, TG_SMEM>>>(J, skip);
    }
    cudaStreamWaitEvent(0, evG3, 0);
    {   // GEMM4: final herb linear (2-term)
        GJobs J{};
        J.j[0] = { hth, htl, wth + WO_OFF, b_out, outp,
                   nullptr, nullptr, nullptr, nullptr, Nh, 128, 0, 0, 0 };
        J.njobs = 1;
        tgemm<<<cdiv(Nh, 128), 256, TG_SMEM>>>(J, skip);
    }
}

// round 17
// speedup vs baseline: 1.1402x; 1.0248x over previous
#include <cuda_runtime.h>
#include <cuda_fp16.h>
#include <cstdint>
#include <math.h>

// ---------------------------------------------------------------------------
// Problem constants
// ---------------------------------------------------------------------------
#define HID 128
#define NHEAD 8
#define HDIM 16

#define NH_MAX 8000
#define NI_MAX 40000
#define NT_MAX 20000
#define NN_MAX (NH_MAX + NI_MAX + NT_MAX)           // 68000
#define NREL_MAX (NH_MAX + 2*NI_MAX + NT_MAX)       // 108000
#define MAXE 250000

// padded K for inputs (multiple of 8 for 16B cp.async alignment)
#define KH 400
#define KI 304
#define KT 200
#define XI_TOTAL ((size_t)NH_MAX*KH + (size_t)NI_MAX*KI + (size_t)NT_MAX*KT)

// fp16 weight pool offsets (transposed [128][Kp])
#define WH_OFF 0
#define WI_OFF 51200
#define WT_OFF 90112
#define WQ_OFF 115712
#define WF_OFF 164864
#define WA_OFF 295936
#define WO_OFF 345088
#define WPOOL  361472

// ---------------------------------------------------------------------------
// Device scratch
// ---------------------------------------------------------------------------
__device__ float g_q    [(size_t)NN_MAX   * HID];
__device__ float g_krel [(size_t)NREL_MAX * HID];
__device__ float g_vrel [(size_t)NREL_MAX * HID];
__device__ float g_bf   [8 * HID];

__device__ int g_deg   [NN_MAX];
__device__ int g_rowptr[NN_MAX + 1];
__device__ int g_pos   [NN_MAX];
__device__ int g_erec  [4 * MAXE];
__device__ int g_bsum  [512];

__device__ __half g_xih[XI_TOTAL];
__device__ __half g_xil[XI_TOTAL];
__device__ __half g_xsh[(size_t)NN_MAX * HID];
__device__ __half g_xsl[(size_t)NN_MAX * HID];
__device__ __half g_gbh[(size_t)NN_MAX * HID];
__device__ __half g_gbl[(size_t)NN_MAX * HID];
__device__ __half g_hth[(size_t)NH_MAX * HID];
__device__ __half g_htl[(size_t)NH_MAX * HID];
__device__ __half g_wth[WPOOL];

// ---------------------------------------------------------------------------
// Fuse Wk/Wv with per-edge-type relation matrices; p_rel/sqrtD folded into
// k-kind. Writes TRANSPOSED fp16 directly into the weight pool.
// ---------------------------------------------------------------------------
__global__ void fuse_rel_weights(const float* __restrict__ Wk, const float* __restrict__ bk,
                                 const float* __restrict__ Wv, const float* __restrict__ bv,
                                 const float* __restrict__ a_rel, const float* __restrict__ m_rel,
                                 const float* __restrict__ prel,
                                 __half* __restrict__ wth, float* __restrict__ bf)
{
    int slot = blockIdx.x;
    int e = slot >> 1, kind = slot & 1;
    int s = (e == 0) ? 0 : ((e == 3) ? 2 : 1);
    const float* Wb = (kind ? Wv : Wk) + (size_t)s * HID * HID;
    const float* bb = (kind ? bv : bk) + (size_t)s * HID;
    const float* rel = (kind ? m_rel : a_rel) + (size_t)e * NHEAD * HDIM * HDIM;

    for (int idx = threadIdx.x; idx < HID * HID; idx += blockDim.x) {
        int i = idx >> 7, j = idx & 127;
        int h = j >> 4, j16 = j & 15;
        float acc = 0.0f;
        #pragma unroll
        for (int d = 0; d < HDIM; ++d)
            acc += Wb[i * HID + h * HDIM + d] * rel[(h * HDIM + d) * HDIM + j16];
        if (kind == 0) acc *= prel[e * NHEAD + h] * 0.25f;
        wth[(size_t)WF_OFF + (size_t)slot * 16384 + j * 128 + i] = __float2half_rn(acc);
    }
    for (int j = threadIdx.x; j < HID; j += blockDim.x) {
        int h = j >> 4, j16 = j & 15;
        float acc = 0.0f;
        #pragma unroll
        for (int d = 0; d < HDIM; ++d)
            acc += bb[h * HDIM + d] * rel[(h * HDIM + d) * HDIM + j16];
        if (kind == 0) acc *= prel[e * NHEAD + h] * 0.25f;
        bf[slot * HID + j] = acc;
    }
}

// ---------------------------------------------------------------------------
// fp32 -> fp16 hi/lo, vectorized (4 elems/thread), with K padding
// ---------------------------------------------------------------------------
__global__ void convert_pad4(const float* __restrict__ src,
                             __half* __restrict__ dh, __half* __restrict__ dl,
                             int M, int K, int Kp)
{
    int idx4 = blockIdx.x * blockDim.x + threadIdx.x;
    int kq = Kp >> 2;
    if (idx4 >= M * kq) return;
    int r = idx4 / kq, k4 = (idx4 - r * kq) << 2;
    float4 v = make_float4(0.f, 0.f, 0.f, 0.f);
    if (k4 < K)
        v = *reinterpret_cast<const float4*>(src + (size_t)r * K + k4);
    __half2 h01, h23, l01, l23;
    h01.x = __float2half_rn(v.x); h01.y = __float2half_rn(v.y);
    h23.x = __float2half_rn(v.z); h23.y = __float2half_rn(v.w);
    l01.x = __float2half_rn(v.x - __half2float(h01.x));
    l01.y = __float2half_rn(v.y - __half2float(h01.y));
    l23.x = __float2half_rn(v.z - __half2float(h23.x));
    l23.y = __float2half_rn(v.w - __half2float(h23.y));
    *reinterpret_cast<__half2*>(dh + (size_t)idx4 * 4)     = h01;
    *reinterpret_cast<__half2*>(dh + (size_t)idx4 * 4 + 2) = h23;
    *reinterpret_cast<__half2*>(dl + (size_t)idx4 * 4)     = l01;
    *reinterpret_cast<__half2*>(dl + (size_t)idx4 * 4 + 2) = l23;
}

// ---------------------------------------------------------------------------
// Weight transpose + fp16: W [K][128] fp32 -> Wt [128][Kp] fp16
// ---------------------------------------------------------------------------
struct TJob { const float* W; __half* th; int K; int Kp; };
struct TJobs { TJob j[10]; };

__global__ void transpose_wt(TJobs jobs)
{
    TJob jb = jobs.j[blockIdx.y];
    int total = 128 * jb.Kp;
    for (int idx = blockIdx.x * blockDim.x + threadIdx.x; idx < total;
         idx += gridDim.x * blockDim.x) {
        int n = idx / jb.Kp, k = idx - n * jb.Kp;
        float v = (k < jb.K) ? jb.W[(size_t)k * 128 + n] : 0.0f;
        jb.th[idx] = __float2half_rn(v);
    }
}

// ---------------------------------------------------------------------------
// CSR build
// ---------------------------------------------------------------------------
struct EArr { const int* src[4]; const int* dst[4]; int E[4]; int base[4]; int slot[4]; };

__global__ void zero_deg(int* __restrict__ deg, int NN)
{
    int i = blockIdx.x * blockDim.x + threadIdx.x;
    if (i < NN) deg[i] = 0;
}

__global__ void hist_deg(EArr ea, int* __restrict__ deg)
{
    int e = blockIdx.y;
    const int* dst = ea.dst[e];
    int E = ea.E[e], base = ea.base[e];
    for (int i = blockIdx.x * blockDim.x + threadIdx.x; i < E;
         i += gridDim.x * blockDim.x)
        atomicAdd(&deg[base + dst[i]], 1);
}

__global__ void scan1(const int* __restrict__ deg, int* __restrict__ rowptr,
                      int* __restrict__ bsum, int NN)
{
    __shared__ int ws[8];
    int i = blockIdx.x * 256 + threadIdx.x;
    int lane = threadIdx.x & 31, w = threadIdx.x >> 5;
    int x = (i < NN) ? deg[i] : 0;
    #pragma unroll
    for (int o = 1; o < 32; o <<= 1) {
        int y = __shfl_up_sync(0xffffffffu, x, o);
        if (lane >= o) x += y;
    }
    if (lane == 31) ws[w] = x;
    __syncthreads();
    if (threadIdx.x < 8) {
        int y = ws[threadIdx.x];
        #pragma unroll
        for (int o = 1; o < 8; o <<= 1) {
            int z = __shfl_up_sync(0xffu, y, o);
            if ((int)threadIdx.x >= o) y += z;
        }
        ws[threadIdx.x] = y;
    }
    __syncthreads();
    if (w > 0) x += ws[w - 1];
    if (i < NN) rowptr[i + 1] = x;
    if (threadIdx.x == 255) bsum[blockIdx.x] = x;
}

__global__ void scan2(int* __restrict__ bsum, int NB)
{
    __shared__ int s[512];
    int t = threadIdx.x;
    int orig = (t < NB) ? bsum[t] : 0;
    s[t] = orig;
    __syncthreads();
    for (int o = 1; o < 512; o <<= 1) {
        int v = (t >= o) ? s[t - o] : 0;
        __syncthreads();
        s[t] += v;
        __syncthreads();
    }
    if (t < NB) bsum[t] = s[t] - orig;
}

__global__ void scan3(const int* __restrict__ deg, int* __restrict__ rowptr,
                      const int* __restrict__ bsum, int* __restrict__ pos, int NN)
{
    int i = blockIdx.x * 256 + threadIdx.x;
    if (i >= NN) return;
    int val = rowptr[i + 1] + bsum[blockIdx.x];
    rowptr[i + 1] = val;
    pos[i] = val - deg[i];
    if (i == 0) rowptr[0] = 0;
}

__global__ void scatter_edges(EArr ea, int* __restrict__ pos, int* __restrict__ erec)
{
    int e = blockIdx.y;
    const int* src = ea.src[e];
    const int* dst = ea.dst[e];
    int E = ea.E[e], base = ea.base[e], slot = ea.slot[e];
    for (int i = blockIdx.x * blockDim.x + threadIdx.x; i < E;
         i += gridDim.x * blockDim.x) {
        int p = atomicAdd(&pos[base + dst[i]], 1);
        erec[p] = slot + src[i];
    }
}

// ---------------------------------------------------------------------------
// Fused attention, node range [n0, n1). One warp per dst node.
// Softmax WITHOUT running-max subtraction: logits are sigma~1 by construction
// (max over all edges ~5.5 sigma; expf overflows at 88 ~ 25+ sigma), so
// den += exp(p); acc += exp(p)*v is safe and removes the serial rescale
// chain (full ILP across edges). 2-deep gather prefetch.
// Writes gelu(agg/den) as fp16 h/l.
// ---------------------------------------------------------------------------
__global__ __launch_bounds__(256)
void attend(const int* __restrict__ rowptr, const int* __restrict__ erec,
            const float* __restrict__ q, const float* __restrict__ krel,
            const float* __restrict__ vrel,
            __half* __restrict__ oh, __half* __restrict__ ol,
            int n0, int n1)
{
    const int n = n0 + ((blockIdx.x * blockDim.x + threadIdx.x) >> 5);
    const int lane = threadIdx.x & 31;
    if (n >= n1) return;

    const int lo = rowptr[n], hi = rowptr[n + 1];
    const float4 qv = *reinterpret_cast<const float4*>(q + (size_t)n * HID + lane * 4);

    float den = 0.0f;
    float4 acc = make_float4(0.f, 0.f, 0.f, 0.f);

    float4 k0, v0, k1, v1;
    if (lo < hi) {
        int ss = __ldg(erec + lo);
        k0 = *reinterpret_cast<const float4*>(krel + (size_t)ss * HID + lane * 4);
        v0 = *reinterpret_cast<const float4*>(vrel + (size_t)ss * HID + lane * 4);
    }
    if (lo + 1 < hi) {
        int ss = __ldg(erec + lo + 1);
        k1 = *reinterpret_cast<const float4*>(krel + (size_t)ss * HID + lane * 4);
        v1 = *reinterpret_cast<const float4*>(vrel + (size_t)ss * HID + lane * 4);
    }
    for (int i = lo; i < hi; ++i) {
        float4 kv = k0, vv = v0;
        k0 = k1; v0 = v1;
        if (i + 2 < hi) {
            int ss = __ldg(erec + i + 2);
            k1 = *reinterpret_cast<const float4*>(krel + (size_t)ss * HID + lane * 4);
            v1 = *reinterpret_cast<const float4*>(vrel + (size_t)ss * HID + lane * 4);
        }
        float p = qv.x * kv.x + qv.y * kv.y + qv.z * kv.z + qv.w * kv.w;
        p += __shfl_xor_sync(0xffffffffu, p, 1);
        p += __shfl_xor_sync(0xffffffffu, p, 2);   // full logit (p_rel folded in)
        float ex = __expf(p);
        den += ex;
        acc.x = fmaf(ex, vv.x, acc.x);
        acc.y = fmaf(ex, vv.y, acc.y);
        acc.z = fmaf(ex, vv.z, acc.z);
        acc.w = fmaf(ex, vv.w, acc.w);
    }

    const float inv = 1.0f / (den + 1e-16f);
    float o[4] = { acc.x * inv, acc.y * inv, acc.z * inv, acc.w * inv };
    #pragma unroll
    for (int j = 0; j < 4; ++j)
        o[j] = 0.5f * o[j] * (1.0f + erff(o[j] * 0.70710678118654752f));
    __half2 h01, h23, l01, l23;
    h01.x = __float2half_rn(o[0]); h01.y = __float2half_rn(o[1]);
    h23.x = __float2half_rn(o[2]); h23.y = __float2half_rn(o[3]);
    l01.x = __float2half_rn(o[0] - __half2float(h01.x));
    l01.y = __float2half_rn(o[1] - __half2float(h01.y));
    l23.x = __float2half_rn(o[2] - __half2float(h23.x));
    l23.y = __float2half_rn(o[3] - __half2float(h23.y));
    size_t ob = (size_t)n * HID + lane * 4;
    *reinterpret_cast<__half2*>(oh + ob)     = h01;
    *reinterpret_cast<__half2*>(oh + ob + 2) = h23;
    *reinterpret_cast<__half2*>(ol + ob)     = l01;
    *reinterpret_cast<__half2*>(ol + ob + 2) = l23;
}

// ---------------------------------------------------------------------------
// fp16 split-precision tensor-core GEMM (mma.sync; compute_103-safe).
// 2-term: D = (Ah + Al) @ B ; 1-term (mode bit3): D = Ah @ B
// mode bit0: skip-gate epilogue (x from fp16 h/l pair)
// mode bit1: write fp16 h/l outputs
// mode bit2: skip fp32 output write
// mode bit3: single-term A (for softmax-bound outputs; halves MMA count)
// ---------------------------------------------------------------------------
#define KC 32
#define PADK 40
#define CHB (128 * PADK)
#define TG_SMEM (6 * CHB * 2)      // 2 stages x 3 arrays (ah, al, b)

struct GJob { const __half *Ah, *Al, *B;
              const float *bias; float *dst;
              const __half *gxh, *gxl;
              __half *dsth, *dstl;
              int M, K, mode, skipidx, blk0; };
struct GJobs { GJob j[11]; int njobs; };

__device__ __forceinline__ uint32_t smem_u32(const void* p) {
    uint32_t a;
    asm("{ .reg .u64 t; cvta.to.shared.u64 t, %1; cvt.u32.u64 %0, t; }" : "=r"(a) : "l"(p));
    return a;
}

#define CPASYNC(dst, src, sz)                                                 \
    asm volatile("cp.async.ca.shared.global [%0], [%1], 16, %2;"              \
        :: "r"(dst), "l"(src), "r"(sz))

#define LDSM4(r0, r1, r2, r3, addr)                                           \
    asm volatile("ldmatrix.sync.aligned.m8n8.x4.shared.b16 {%0,%1,%2,%3}, [%4];" \
        : "=r"(r0), "=r"(r1), "=r"(r2), "=r"(r3) : "r"(addr))

#define MMA_FP16(d, a, b)                                                     \
    asm volatile("mma.sync.aligned.m16n8k16.row.col.f32.f16.f16.f32 "         \
        "{%0,%1,%2,%3}, {%4,%5,%6,%7}, {%8,%9}, {%0,%1,%2,%3};"               \
        : "+f"((d)[0]), "+f"((d)[1]), "+f"((d)[2]), "+f"((d)[3])              \
        : "r"((a)[0]), "r"((a)[1]), "r"((a)[2]), "r"((a)[3]),                 \
          "r"((b)[0]), "r"((b)[1]))

__global__ __launch_bounds__(256, 2)
void tgemm(GJobs jobs, const float* __restrict__ skipv)
{
    extern __shared__ __half sm[];
    const uint32_t base = smem_u32(sm);
    const int tid = threadIdx.x;
    const int wid = tid >> 5, lane = tid & 31;
    const int wm = wid & 1, wn = wid >> 1;

    int ji = 0;
    #pragma unroll 1
    for (int t = 1; t < jobs.njobs; ++t)
        if ((int)blockIdx.x >= jobs.j[t].blk0) ji = t;
    const GJob jb = jobs.j[ji];
    const int m0 = ((int)blockIdx.x - jb.blk0) * 128;
    const int M = jb.M, K = jb.K;
    const bool twoTerm = !(jb.mode & 8);

    float acc[4][4][4];
    #pragma unroll
    for (int mi = 0; mi < 4; ++mi)
        #pragma unroll
        for (int ni = 0; ni < 4; ++ni)
            #pragma unroll
            for (int r = 0; r < 4; ++r) acc[mi][ni][r] = 0.0f;

    const int a_row = ((lane >> 3) & 1) * 8 + (lane & 7);
    const int a_col = (lane >> 4) * 8;
    const int b_row = (lane >> 4) * 8 + (lane & 7);
    const int b_col = ((lane >> 3) & 1) * 8;

    const int lr = tid >> 2;
    const int lk = (tid & 3) * 8;

    const int kch = (K + KC - 1) / KC;

    auto load_chunk = [&](int c, int b) {
        const int k0 = c * KC;
        const uint32_t bb = base + (uint32_t)b * (3 * CHB * 2);
        #pragma unroll
        for (int i = 0; i < 2; ++i) {
            int r = lr + i * 64;
            int gk = k0 + lk;
            uint32_t off = (uint32_t)(r * PADK + lk) * 2;
            int okA = (m0 + r < M) && (gk < K) ? 16 : 0;
            size_t aoff = okA ? ((size_t)(m0 + r) * K + gk) : 0;
            CPASYNC(bb + off, jb.Ah + aoff, okA);
            if (twoTerm)
                CPASYNC(bb + off + CHB * 2, jb.Al + aoff, okA);
            int okB = (gk < K) ? 16 : 0;
            size_t boff = okB ? ((size_t)r * K + gk) : 0;
            CPASYNC(bb + off + 2 * CHB * 2, jb.B + boff, okB);
        }
        asm volatile("cp.async.commit_group;" ::: "memory");
    };

    load_chunk(0, 0);

    for (int c = 0; c < kch; ++c) {
        const int b = c & 1;
        asm volatile("cp.async.wait_group 0;" ::: "memory");
        // one barrier: publishes buf b AND orders prior compute on b^1
        // before the load below overwrites it
        __syncthreads();
        if (c + 1 < kch) load_chunk(c + 1, b ^ 1);

        const uint32_t bb = base + (uint32_t)b * (3 * CHB * 2);
        #pragma unroll
        for (int kk = 0; kk < 2; ++kk) {
            uint32_t ah[4][4], al[4][4], bf2[4][2];
            #pragma unroll
            for (int mi = 0; mi < 4; ++mi) {
                int row = wm * 64 + mi * 16 + a_row;
                int col = kk * 16 + a_col;
                uint32_t off = bb + (uint32_t)(row * PADK + col) * 2;
                LDSM4(ah[mi][0], ah[mi][1], ah[mi][2], ah[mi][3], off);
                if (twoTerm)
                    LDSM4(al[mi][0], al[mi][1], al[mi][2], al[mi][3], off + CHB * 2);
            }
            #pragma unroll
            for (int p = 0; p < 2; ++p) {
                int row = wn * 32 + p * 16 + b_row;
                int col = kk * 16 + b_col;
                uint32_t off = bb + 2 * CHB * 2 + (uint32_t)(row * PADK + col) * 2;
                LDSM4(bf2[2*p][0], bf2[2*p][1], bf2[2*p+1][0], bf2[2*p+1][1], off);
            }
            #pragma unroll
            for (int mi = 0; mi < 4; ++mi)
                #pragma unroll
                for (int ni = 0; ni < 4; ++ni) {
                    MMA_FP16(acc[mi][ni], ah[mi], bf2[ni]);
                    if (twoTerm)
                        MMA_FP16(acc[mi][ni], al[mi], bf2[ni]);
                }
        }
    }

    float g = 0.f, hg = 0.f;
    if (jb.mode & 1) {
        g = 1.f / (1.f + expf(-skipv[jb.skipidx]));
        hg = 1.f - g;
    }
    const int r4 = lane >> 2, c2 = (lane & 3) * 2;
    #pragma unroll
    for (int mi = 0; mi < 4; ++mi) {
        #pragma unroll
        for (int ni = 0; ni < 4; ++ni) {
            int gcol = wn * 32 + ni * 8 + c2;
            float2 bb2 = *reinterpret_cast<const float2*>(jb.bias + gcol);
            #pragma unroll
            for (int half = 0; half < 2; ++half) {
                int gr = m0 + wm * 64 + mi * 16 + r4 + half * 8;
                if (gr >= M) continue;
                float2 o;
                o.x = acc[mi][ni][half * 2 + 0] + bb2.x;
                o.y = acc[mi][ni][half * 2 + 1] + bb2.y;
                if (jb.mode & 1) {
                    __half2 xh2 = *reinterpret_cast<const __half2*>(
                        jb.gxh + (size_t)gr * HID + gcol);
                    __half2 xl2 = *reinterpret_cast<const __half2*>(
                        jb.gxl + (size_t)gr * HID + gcol);
                    float xx = __half2float(xh2.x) + __half2float(xl2.x);
                    float xy = __half2float(xh2.y) + __half2float(xl2.y);
                    o.x = fmaxf(0.f, g * o.x + hg * xx);
                    o.y = fmaxf(0.f, g * o.y + hg * xy);
                }
                if (!(jb.mode & 4))
                    *reinterpret_cast<float2*>(jb.dst + (size_t)gr * HID + gcol) = o;
                if (jb.mode & 2) {
                    __half2 h2, l2;
                    h2.x = __float2half_rn(o.x);
                    h2.y = __float2half_rn(o.y);
                    l2.x = __float2half_rn(o.x - __half2float(h2.x));
                    l2.y = __float2half_rn(o.y - __half2float(h2.y));
                    *reinterpret_cast<__half2*>(jb.dsth + (size_t)gr * HID + gcol) = h2;
                    *reinterpret_cast<__half2*>(jb.dstl + (size_t)gr * HID + gcol) = l2;
                }
            }
        }
    }
}

// ---------------------------------------------------------------------------
static inline int cdiv(int a, int b) { return (a + b - 1) / b; }

extern "C" void kernel_launch(void* const* d_in, const int* in_sizes, int n_in,
                              void* d_out, int out_size)
{
    const float* x_herb = (const float*)d_in[0];
    const float* x_ing  = (const float*)d_in[1];
    const float* x_tgt  = (const float*)d_in[2];
    const float* W_herb = (const float*)d_in[3];
    const float* b_herb = (const float*)d_in[4];
    const float* W_ing  = (const float*)d_in[5];
    const float* b_ing  = (const float*)d_in[6];
    const float* W_tgt  = (const float*)d_in[7];
    const float* b_tgt  = (const float*)d_in[8];
    const float* Wk     = (const float*)d_in[9];
    const float* bk     = (const float*)d_in[10];
    const float* Wq     = (const float*)d_in[11];
    const float* bq     = (const float*)d_in[12];
    const float* Wv     = (const float*)d_in[13];
    const float* bv     = (const float*)d_in[14];
    const float* a_rel  = (const float*)d_in[15];
    const float* m_rel  = (const float*)d_in[16];
    const float* p_rel  = (const float*)d_in[17];
    const float* Wa     = (const float*)d_in[18];
    const float* ba     = (const float*)d_in[19];
    const float* skip   = (const float*)d_in[20];
    const float* W_out  = (const float*)d_in[21];
    const float* b_out  = (const float*)d_in[22];
    const int* src_e[4] = { (const int*)d_in[23], (const int*)d_in[25],
                            (const int*)d_in[27], (const int*)d_in[29] };
    const int* dst_e[4] = { (const int*)d_in[24], (const int*)d_in[26],
                            (const int*)d_in[28], (const int*)d_in[30] };

    const int Nh = in_sizes[0] / 400;
    const int Ni = in_sizes[1] / 300;
    const int Nt = in_sizes[2] / 200;
    const int NN = Nh + Ni + Nt;
    int E[4] = { in_sizes[23], in_sizes[25], in_sizes[27], in_sizes[29] };

    float *q, *krel, *vrel, *bfp;
    cudaGetSymbolAddress((void**)&q, g_q);
    cudaGetSymbolAddress((void**)&krel, g_krel);
    cudaGetSymbolAddress((void**)&vrel, g_vrel);
    cudaGetSymbolAddress((void**)&bfp, g_bf);

    int *deg, *rowptr, *pos, *erec, *bsum;
    cudaGetSymbolAddress((void**)&deg, g_deg);
    cudaGetSymbolAddress((void**)&rowptr, g_rowptr);
    cudaGetSymbolAddress((void**)&pos, g_pos);
    cudaGetSymbolAddress((void**)&erec, g_erec);
    cudaGetSymbolAddress((void**)&bsum, g_bsum);

    __half *xih, *xil, *xsh, *xsl, *gbh, *gbl, *hth, *htl, *wth;
    cudaGetSymbolAddress((void**)&xih, g_xih);
    cudaGetSymbolAddress((void**)&xil, g_xil);
    cudaGetSymbolAddress((void**)&xsh, g_xsh);
    cudaGetSymbolAddress((void**)&xsl, g_xsl);
    cudaGetSymbolAddress((void**)&gbh, g_gbh);
    cudaGetSymbolAddress((void**)&gbl, g_gbl);
    cudaGetSymbolAddress((void**)&hth, g_hth);
    cudaGetSymbolAddress((void**)&htl, g_htl);
    cudaGetSymbolAddress((void**)&wth, g_wth);

    cudaFuncSetAttribute(tgemm, cudaFuncAttributeMaxDynamicSharedMemorySize, TG_SMEM);

    static cudaStream_t sB = nullptr, sC = nullptr;
    static cudaEvent_t evRoot = nullptr, evC = nullptr, evT = nullptr,
                       ev2a = nullptr, ev2b = nullptr, evAH = nullptr,
                       evG3 = nullptr;
    if (sB == nullptr) {
        cudaStreamCreateWithFlags(&sB, cudaStreamNonBlocking);
        cudaStreamCreateWithFlags(&sC, cudaStreamNonBlocking);
        cudaEventCreateWithFlags(&evRoot, cudaEventDisableTiming);
        cudaEventCreateWithFlags(&evC, cudaEventDisableTiming);
        cudaEventCreateWithFlags(&evT, cudaEventDisableTiming);
        cudaEventCreateWithFlags(&ev2a, cudaEventDisableTiming);
        cudaEventCreateWithFlags(&ev2b, cudaEventDisableTiming);
        cudaEventCreateWithFlags(&evAH, cudaEventDisableTiming);
        cudaEventCreateWithFlags(&evG3, cudaEventDisableTiming);
    }

    const int offT3[3]   = { 0, Nh, Nh + Ni };
    const int slotOff[4] = { 0, Nh, Nh + Ni, Nh + 2 * Ni };
    const int dstOff[4]  = { Nh, 0, Nh + Ni, Nh };
    const int Ntype[3]   = { Nh, Ni, Nt };

    EArr ea;
    for (int e = 0; e < 4; ++e) {
        ea.src[e] = src_e[e]; ea.dst[e] = dst_e[e];
        ea.E[e] = E[e]; ea.base[e] = dstOff[e]; ea.slot[e] = slotOff[e];
    }

    // fork
    cudaEventRecord(evRoot, 0);
    cudaStreamWaitEvent(sB, evRoot, 0);
    cudaStreamWaitEvent(sC, evRoot, 0);

    // ---- stream B: CSR build
    zero_deg<<<cdiv(NN, 256), 256, 0, sB>>>(deg, NN);
    hist_deg<<<dim3(128, 4), 256, 0, sB>>>(ea, deg);
    const int NB = cdiv(NN, 256);
    scan1<<<NB, 256, 0, sB>>>(deg, rowptr, bsum, NN);
    scan2<<<1, 512, 0, sB>>>(bsum, NB);
    scan3<<<NB, 256, 0, sB>>>(deg, rowptr, bsum, pos, NN);
    scatter_edges<<<dim3(128, 4), 256, 0, sB>>>(ea, pos, erec);

    // ---- stream C: input converts + weight transposes, then GEMM1-tgt
    const size_t xiI = (size_t)Nh * KH;
    const size_t xiT = xiI + (size_t)Ni * KI;
    convert_pad4<<<cdiv(Nh * KH / 4, 256), 256, 0, sC>>>(x_herb, xih,       xil,       Nh, 400, KH);
    convert_pad4<<<cdiv(Ni * KI / 4, 256), 256, 0, sC>>>(x_ing,  xih + xiI, xil + xiI, Ni, 300, KI);
    convert_pad4<<<cdiv(Nt * KT / 4, 256), 256, 0, sC>>>(x_tgt,  xih + xiT, xil + xiT, Nt, 200, KT);
    {
        TJobs T{};
        int t = 0;
        T.j[t++] = { W_herb, wth + WH_OFF, 400, KH };
        T.j[t++] = { W_ing,  wth + WI_OFF, 300, KI };
        T.j[t++] = { W_tgt,  wth + WT_OFF, 200, KT };
        for (int i = 0; i < 3; ++i)
            T.j[t++] = { Wq + (size_t)i*HID*HID, wth + WQ_OFF + i*16384, 128, 128 };
        for (int i = 0; i < 3; ++i)
            T.j[t++] = { Wa + (size_t)i*HID*HID, wth + WA_OFF + i*16384, 128, 128 };
        T.j[t++] = { W_out, wth + WO_OFF, 128, 128 };
        transpose_wt<<<dim3(64, 10), 256, 0, sC>>>(T);
    }
    cudaEventRecord(evC, sC);
    {   // GEMM1-tgt on stream C (concurrent with main's GEMM1 h+i); only
        // needs convert-tgt + transpose-WT, both earlier in this stream
        GJobs J{};
        J.j[0] = { xih + xiT, xil + xiT, wth + WT_OFF, b_tgt, nullptr,
                   nullptr, nullptr,
                   xsh + (size_t)(Nh+Ni)*HID, xsl + (size_t)(Nh+Ni)*HID,
                   Nt, KT, 6, 0, 0 };
        J.njobs = 1;
        tgemm<<<cdiv(Nt, 128), 256, TG_SMEM, sC>>>(J, skip);
    }
    cudaEventRecord(evT, sC);

    // ---- main stream: fuse then dense chain
    fuse_rel_weights<<<8, 256>>>(Wk, bk, Wv, bv, a_rel, m_rel, p_rel, wth, bfp);
    cudaStreamWaitEvent(0, evC, 0);

    // GEMM1 (herb + ing only) -> xs fp16 h/l (2-term)
    {
        GJobs J{}; int nb = 0;
        auto add = [&](const __half* ah, const __half* al, int woff,
                       const float* b, __half* dh, __half* dl, int M, int K) {
            J.j[J.njobs] = { ah, al, wth + woff, b, nullptr,
                             nullptr, nullptr, dh, dl, M, K, 6, 0, nb };
            J.njobs++; nb += cdiv(M, 128);
        };
        add(xih,       xil,       WH_OFF, b_herb,
            xsh,                  xsl,                  Nh, KH);
        add(xih + xiI, xil + xiI, WI_OFF, b_ing,
            xsh + (size_t)Nh*HID, xsl + (size_t)Nh*HID, Ni, KI);
        tgemm<<<nb, 256, TG_SMEM>>>(J, skip);
    }

    // GEMM2a: herb-attend prerequisites (q_herb 2-term; kr1/vr1 single-term)
    {
        GJobs J{}; int nb = 0;
        auto add = [&](int xoff, int woff, const float* b, float* d, int M, int mode) {
            J.j[J.njobs] = { xsh + (size_t)xoff*HID, xsl + (size_t)xoff*HID,
                             wth + woff, b, d,
                             nullptr, nullptr, nullptr, nullptr, M, 128, mode, 0, nb };
            J.njobs++; nb += cdiv(M, 128);
        };
        add(0,  WQ_OFF,           bq,          q,                             Nh, 0);
        add(Nh, WF_OFF + 2*16384, bfp + 2*HID, krel + (size_t)slotOff[1]*HID, Ni, 8);
        add(Nh, WF_OFF + 3*16384, bfp + 3*HID, vrel + (size_t)slotOff[1]*HID, Ni, 8);
        tgemm<<<nb, 256, TG_SMEM>>>(J, skip);
    }
    cudaEventRecord(ev2a, 0);

    // GEMM2b needs xs_tgt (stream C) for its tgt jobs
    cudaStreamWaitEvent(0, evT, 0);

    // GEMM2b: remaining projections (q 2-term; kr/vr single-term)
    {
        GJobs J{}; int nb = 0;
        auto add = [&](int xoff, int woff, const float* b, float* d, int M, int mode) {
            J.j[J.njobs] = { xsh + (size_t)xoff*HID, xsl + (size_t)xoff*HID,
                             wth + woff, b, d,
                             nullptr, nullptr, nullptr, nullptr, M, 128, mode, 0, nb };
            J.njobs++; nb += cdiv(M, 128);
        };
        add(Nh,      WQ_OFF + 1*16384, bq + 1*HID,  q + (size_t)Nh*HID,            Ni, 0);
        add(0,       WF_OFF + 0*16384, bfp + 0*HID, krel + (size_t)slotOff[0]*HID, Nh, 8);
        add(0,       WF_OFF + 1*16384, bfp + 1*HID, vrel + (size_t)slotOff[0]*HID, Nh, 8);
        add(Nh,      WF_OFF + 4*16384, bfp + 4*HID, krel + (size_t)slotOff[2]*HID, Ni, 8);
        add(Nh,      WF_OFF + 5*16384, bfp + 5*HID, vrel + (size_t)slotOff[2]*HID, Ni, 8);
        add(Nh + Ni, WQ_OFF + 2*16384, bq + 2*HID,  q + (size_t)(Nh+Ni)*HID,       Nt, 0);
        add(Nh + Ni, WF_OFF + 6*16384, bfp + 6*HID, krel + (size_t)slotOff[3]*HID, Nt, 8);
        add(Nh + Ni, WF_OFF + 7*16384, bfp + 7*HID, vrel + (size_t)slotOff[3]*HID, Nt, 8);
        tgemm<<<nb, 256, TG_SMEM>>>(J, skip);
    }
    cudaEventRecord(ev2b, 0);

    // ---- stream B: herb attend, then rest + GEMM3 ing/tgt
    float* outp = (float*)d_out;
    cudaStreamWaitEvent(sB, ev2a, 0);
    attend<<<cdiv(Nh * 32, 256), 256, 0, sB>>>(rowptr, erec, q, krel, vrel,
                                               gbh, gbl, 0, Nh);
    cudaEventRecord(evAH, sB);
    cudaStreamWaitEvent(sB, ev2b, 0);
    attend<<<cdiv((NN - Nh) * 32, 256), 256, 0, sB>>>(rowptr, erec, q, krel, vrel,
                                                      gbh, gbl, Nh, NN);
    {   // GEMM3 ing + tgt -> d_out directly (2-term)
        GJobs J{}; int nb = 0;
        for (int i = 1; i < 3; ++i) {
            float* d = (i == 1) ? outp + (size_t)Nh*HID : outp + (size_t)(Nh+Ni)*HID;
            J.j[J.njobs] = { gbh + (size_t)offT3[i]*HID, gbl + (size_t)offT3[i]*HID,
                             wth + WA_OFF + i*16384, ba + i*HID, d,
                             xsh + (size_t)offT3[i]*HID, xsl + (size_t)offT3[i]*HID,
                             nullptr, nullptr, Ntype[i], 128, 1, i, nb };
            J.njobs++; nb += cdiv(Ntype[i], 128);
        }
        tgemm<<<nb, 256, TG_SMEM, sB>>>(J, skip);
    }
    cudaEventRecord(evG3, sB);

    // ---- main: herb output chain
    cudaStreamWaitEvent(0, evAH, 0);
    {   // GEMM3 herb -> hth/htl (fp16 h/l only, 2-term)
        GJobs J{};
        J.j[0] = { gbh, gbl, wth + WA_OFF, ba, nullptr,
                   xsh, xsl, hth, htl, Nh, 128, 1 | 2 | 4, 0, 0 };
        J.njobs = 1;
        tgemm<<<cdiv(Nh, 128), 256, TG_SMEM>>>(J, skip);
    }
    cudaStreamWaitEvent(0, evG3, 0);
    {   // GEMM4: final herb linear (2-term)
        GJobs J{};
        J.j[0] = { hth, htl, wth + WO_OFF, b_out, outp,
                   nullptr, nullptr, nullptr, nullptr, Nh, 128, 0, 0, 0 };
        J.njobs = 1;
        tgemm<<<cdiv(Nh, 128), 256, TG_SMEM>>>(J, skip);
    }
}